// round 1
// baseline (speedup 1.0000x reference)
#include <cuda_runtime.h>
#include <cuda_bf16.h>
#include <math.h>

// Problem constants
#define Bsz 2
#define Tn 4096
#define Dm 2048
#define Hh 8
#define DK 128
#define DV 256
#define Wc 4
#define BH (Bsz*Hh)          // 16
#define QKC (Hh*DK)          // 1024
#define VC  (Hh*DV)          // 2048

// ---------------- scratch (device globals; no allocations allowed) -------------
__device__ float g_qpre[(size_t)Bsz*Tn*QKC];
__device__ float g_kpre[(size_t)Bsz*Tn*QKC];
__device__ float g_vpre[(size_t)Bsz*Tn*VC];
__device__ float g_gate[(size_t)Bsz*Tn*VC];
__device__ float g_ba  [(size_t)Bsz*Tn*16];
__device__ float g_Wba [(size_t)Dm*16];
__device__ float g_qn  [(size_t)BH*Tn*DK];
__device__ float g_kn  [(size_t)BH*Tn*DK];
__device__ float g_vc  [(size_t)BH*Tn*DV];
__device__ float g_eg  [(size_t)BH*Tn];
__device__ float g_beta[(size_t)BH*Tn];
__device__ float g_o   [(size_t)BH*Tn*DV];
__device__ float g_on  [(size_t)Bsz*Tn*VC];

// ---------------- generic fp32 tiled GEMM: C[M,N] = A[M,K] @ B[K,N] ------------
// M multiple of 64, K multiple of 16, N arbitrary (guarded).
#define BM 64
#define BN 64
#define BKK 16
__global__ void gemm_kernel(const float* __restrict__ A, const float* __restrict__ B,
                            float* __restrict__ C, int M, int N, int K) {
    __shared__ float sA[BKK][BM + 1];
    __shared__ float sB[BKK][BN];
    int tid = threadIdx.x;           // 256 threads
    int bx = blockIdx.x, by = blockIdx.y;
    int row0 = by * BM, col0 = bx * BN;
    int tx = tid & 15, ty = tid >> 4;

    float acc[4][4];
#pragma unroll
    for (int i = 0; i < 4; i++)
#pragma unroll
        for (int j = 0; j < 4; j++) acc[i][j] = 0.f;

    for (int k0 = 0; k0 < K; k0 += BKK) {
#pragma unroll
        for (int l = 0; l < 4; l++) {
            int linear = tid + l * 256;      // 0..1023
            int r  = linear >> 4;
            int kk = linear & 15;
            sA[kk][r] = A[(size_t)(row0 + r) * K + k0 + kk];
        }
#pragma unroll
        for (int l = 0; l < 4; l++) {
            int linear = tid + l * 256;
            int kk = linear >> 6;
            int c  = linear & 63;
            float v = 0.f;
            if (col0 + c < N) v = B[(size_t)(k0 + kk) * N + col0 + c];
            sB[kk][c] = v;
        }
        __syncthreads();
#pragma unroll
        for (int kk = 0; kk < BKK; kk++) {
            float a[4];
#pragma unroll
            for (int i = 0; i < 4; i++) a[i] = sA[kk][ty * 4 + i];
            float4 bv = *reinterpret_cast<const float4*>(&sB[kk][tx * 4]);
            float b[4] = {bv.x, bv.y, bv.z, bv.w};
#pragma unroll
            for (int i = 0; i < 4; i++)
#pragma unroll
                for (int j = 0; j < 4; j++) acc[i][j] += a[i] * b[j];
        }
        __syncthreads();
    }
#pragma unroll
    for (int i = 0; i < 4; i++) {
        int r = row0 + ty * 4 + i;
#pragma unroll
        for (int j = 0; j < 4; j++) {
            int c = col0 + tx * 4 + j;
            if (c < N) C[(size_t)r * N + c] = acc[i][j];
        }
    }
}

// ---------------- concat Wb|Wa -> [K,16] ---------------------------------------
__global__ void concat_ba_kernel(const float* __restrict__ Wb, const float* __restrict__ Wa) {
    int k = blockIdx.x * blockDim.x + threadIdx.x;
    if (k < Dm) {
#pragma unroll
        for (int j = 0; j < 8; j++) {
            g_Wba[(size_t)k * 16 + j]     = Wb[(size_t)k * 8 + j];
            g_Wba[(size_t)k * 16 + 8 + j] = Wa[(size_t)k * 8 + j];
        }
    }
}

__device__ __forceinline__ float siluf(float x) { return x / (1.f + __expf(-x)); }

// ---------------- causal dwconv + silu + l2norm for q/k ------------------------
// pre: [B,T,1024], convw: [1024,4], out: [BH][T][128]
__global__ void convnorm_qk_kernel(const float* __restrict__ pre,
                                   const float* __restrict__ convw,
                                   float* __restrict__ out, float scale) {
    int idx = blockIdx.x;                 // (b*T + t)*H + h
    int h = idx % Hh;
    int t = (idx / Hh) % Tn;
    int b = idx / (Hh * Tn);
    int c = h * DK + threadIdx.x;         // 128 threads

    const float* base = pre + (size_t)b * Tn * QKC;
    float acc = 0.f;
#pragma unroll
    for (int i = 0; i < Wc; i++) {
        int tt = t - (Wc - 1) + i;
        if (tt >= 0) acc += base[(size_t)tt * QKC + c] * convw[(size_t)c * Wc + i];
    }
    float s = siluf(acc);
    float ss = s * s;
#pragma unroll
    for (int m = 16; m; m >>= 1) ss += __shfl_xor_sync(0xffffffffu, ss, m);
    __shared__ float wsum[4];
    if ((threadIdx.x & 31) == 0) wsum[threadIdx.x >> 5] = ss;
    __syncthreads();
    float tot = wsum[0] + wsum[1] + wsum[2] + wsum[3];
    float r = rsqrtf(tot + 1e-6f) * scale;
    out[(((size_t)(b * Hh + h) * Tn) + t) * DK + threadIdx.x] = s * r;
}

// ---------------- causal dwconv + silu for v -----------------------------------
// pre: [B,T,2048] -> vc: [BH][T][256]
__global__ void convsilu_v_kernel(const float* __restrict__ pre,
                                  const float* __restrict__ convw) {
    size_t total = (size_t)Bsz * Tn * VC;
    for (size_t idx = (size_t)blockIdx.x * blockDim.x + threadIdx.x;
         idx < total; idx += (size_t)gridDim.x * blockDim.x) {
        int c = idx % VC;
        int t = (idx / VC) % Tn;
        int b = idx / ((size_t)VC * Tn);
        int h = c / DV, dv = c % DV;
        const float* base = pre + (size_t)b * Tn * VC;
        float acc = 0.f;
#pragma unroll
        for (int i = 0; i < Wc; i++) {
            int tt = t - (Wc - 1) + i;
            if (tt >= 0) acc += base[(size_t)tt * VC + c] * convw[(size_t)c * Wc + i];
        }
        g_vc[(((size_t)(b * Hh + h) * Tn) + t) * DV + dv] = siluf(acc);
    }
}

// ---------------- beta / exp(g) -------------------------------------------------
__global__ void betag_kernel(const float* __restrict__ A_log,
                             const float* __restrict__ dt_bias) {
    int idx = blockIdx.x * blockDim.x + threadIdx.x;   // (b*T+t)*H + h
    if (idx >= Bsz * Tn * Hh) return;
    int h = idx % Hh;
    int t = (idx / Hh) % Tn;
    int b = idx / (Hh * Tn);
    float bpre = g_ba[(size_t)(b * Tn + t) * 16 + h];
    float apre = g_ba[(size_t)(b * Tn + t) * 16 + 8 + h];
    float beta = 1.f / (1.f + expf(-bpre));
    float xg = apre + dt_bias[h];
    float sp = (xg > 20.f) ? xg : log1pf(expf(xg));
    float gg = -expf(A_log[h]) * sp;
    size_t o = (size_t)(b * Hh + h) * Tn + t;
    g_eg[o] = expf(gg);
    g_beta[o] = beta;
}

// ---------------- gated delta-rule recurrence ----------------------------------
// grid: (BH, DV/DVT). block: DVT*4 threads. Each thread owns 32 rows of one
// S column in registers. Sequential over T, chunk-staged smem for k/q/v/g/beta.
#define DVT 32
#define STAGE 32
#define SUBW 36   // skewed sub-row stride (words) -> conflict-free 4-way access

__global__ void __launch_bounds__(DVT*4, 1) delta_kernel() {
    int bh = blockIdx.x;
    int vt = blockIdx.y;
    int tid = threadIdx.x;           // 128
    int col = tid >> 2;              // 0..31 (tile-local column)
    int sub = tid & 3;               // row group: rows [sub*32, sub*32+32)
    int gcol = vt * DVT + col;

    const float* kb  = g_kn   + (size_t)bh * Tn * DK;
    const float* qb  = g_qn   + (size_t)bh * Tn * DK;
    const float* vb  = g_vc   + (size_t)bh * Tn * DV;
    const float* egb = g_eg   + (size_t)bh * Tn;
    const float* btb = g_beta + (size_t)bh * Tn;
    float* ob        = g_o    + (size_t)bh * Tn * DV;

    __shared__ float sK[STAGE][4 * SUBW];
    __shared__ float sQ[STAGE][4 * SUBW];
    __shared__ float sV[STAGE][DVT];
    __shared__ float sEg[STAGE];
    __shared__ float sBt[STAGE];

    float S[32];
#pragma unroll
    for (int i = 0; i < 32; i++) S[i] = 0.f;

    for (int c0 = 0; c0 < Tn; c0 += STAGE) {
        __syncthreads();
        // cooperative stage loads (STAGE*128 floats = 1024 float4 for K and Q)
#pragma unroll
        for (int l = 0; l < 8; l++) {
            int linear = tid + l * 128;          // 0..1023 float4 index
            int tl = linear >> 5;                // step
            int v4 = linear & 31;                // float4 within row
            float4 kv = reinterpret_cast<const float4*>(kb + (size_t)(c0 + tl) * DK)[v4];
            float4 qv = reinterpret_cast<const float4*>(qb + (size_t)(c0 + tl) * DK)[v4];
            int off = (v4 >> 3) * SUBW + (v4 & 7) * 4;
            *reinterpret_cast<float4*>(&sK[tl][off]) = kv;
            *reinterpret_cast<float4*>(&sQ[tl][off]) = qv;
        }
        // V tile: STAGE*DVT = 1024 floats = 256 float4
#pragma unroll
        for (int l = 0; l < 2; l++) {
            int linear = tid + l * 128;          // 0..255
            int tl = linear >> 3;
            int v4 = linear & 7;
            float4 vv = reinterpret_cast<const float4*>(vb + (size_t)(c0 + tl) * DV + vt * DVT)[v4];
            *reinterpret_cast<float4*>(&sV[tl][v4 * 4]) = vv;
        }
        if (tid < STAGE) {
            sEg[tid] = egb[c0 + tid];
            sBt[tid] = btb[c0 + tid];
        }
        __syncthreads();

        for (int s = 0; s < STAGE; s++) {
            float eg = sEg[s];
            const float4* kr = reinterpret_cast<const float4*>(&sK[s][sub * SUBW]);
            const float4* qr = reinterpret_cast<const float4*>(&sQ[s][sub * SUBW]);

            float4 kq[8];
#pragma unroll
            for (int j = 0; j < 8; j++) kq[j] = kr[j];

            // p = k . S (partial over 32 rows)
            float p0 = 0.f, p1 = 0.f, p2 = 0.f, p3 = 0.f;
#pragma unroll
            for (int j = 0; j < 8; j++) {
                p0 += kq[j].x * S[4 * j + 0];
                p1 += kq[j].y * S[4 * j + 1];
                p2 += kq[j].z * S[4 * j + 2];
                p3 += kq[j].w * S[4 * j + 3];
            }
            float p = (p0 + p1) + (p2 + p3);
            p += __shfl_xor_sync(0xffffffffu, p, 1);
            p += __shfl_xor_sync(0xffffffffu, p, 2);

            float w = sBt[s] * (sV[s][col] - eg * p);

            // S = eg*S + k*w ; o = q . S_new
            float o0 = 0.f, o1 = 0.f, o2 = 0.f, o3 = 0.f;
#pragma unroll
            for (int j = 0; j < 8; j++) {
                float4 qv = qr[j];
                S[4 * j + 0] = eg * S[4 * j + 0] + kq[j].x * w;
                S[4 * j + 1] = eg * S[4 * j + 1] + kq[j].y * w;
                S[4 * j + 2] = eg * S[4 * j + 2] + kq[j].z * w;
                S[4 * j + 3] = eg * S[4 * j + 3] + kq[j].w * w;
                o0 += qv.x * S[4 * j + 0];
                o1 += qv.y * S[4 * j + 1];
                o2 += qv.z * S[4 * j + 2];
                o3 += qv.w * S[4 * j + 3];
            }
            float o = (o0 + o1) + (o2 + o3);
            o += __shfl_xor_sync(0xffffffffu, o, 1);
            o += __shfl_xor_sync(0xffffffffu, o, 2);
            if (sub == 0) ob[(size_t)(c0 + s) * DV + gcol] = o;
        }
    }
}

// ---------------- gated RMSNorm + silu(gate) -----------------------------------
__global__ void gatednorm_kernel(const float* __restrict__ g_norm_w) {
    int idx = blockIdx.x;                 // (b*T + t)*H + h
    int h = idx % Hh;
    int t = (idx / Hh) % Tn;
    int b = idx / (Hh * Tn);
    int dv = threadIdx.x;                 // 256
    size_t obase = ((size_t)(b * Hh + h) * Tn + t) * DV;
    float o = g_o[obase + dv];
    float ss = o * o;
#pragma unroll
    for (int m = 16; m; m >>= 1) ss += __shfl_xor_sync(0xffffffffu, ss, m);
    __shared__ float wsum[8];
    if ((threadIdx.x & 31) == 0) wsum[threadIdx.x >> 5] = ss;
    __syncthreads();
    float tot = 0.f;
#pragma unroll
    for (int i = 0; i < 8; i++) tot += wsum[i];
    float r = rsqrtf(tot * (1.f / DV) + 1e-5f);
    size_t gidx = ((size_t)(b * Tn + t)) * VC + h * DV + dv;
    float gt = g_gate[gidx];
    g_on[gidx] = o * r * g_norm_w[dv] * siluf(gt);
}

// ---------------- launch --------------------------------------------------------
extern "C" void kernel_launch(void* const* d_in, const int* in_sizes, int n_in,
                              void* d_out, int out_size) {
    const float* x       = (const float*)d_in[0];
    const float* Wq      = (const float*)d_in[1];
    const float* Wk      = (const float*)d_in[2];
    const float* Wv      = (const float*)d_in[3];
    const float* Wb      = (const float*)d_in[4];
    const float* Wa      = (const float*)d_in[5];
    const float* Wg      = (const float*)d_in[6];
    const float* Wo      = (const float*)d_in[7];
    const float* conv_q  = (const float*)d_in[8];
    const float* conv_k  = (const float*)d_in[9];
    const float* conv_v  = (const float*)d_in[10];
    const float* A_log   = (const float*)d_in[11];
    const float* dt_bias = (const float*)d_in[12];
    const float* gnw     = (const float*)d_in[13];
    float* out = (float*)d_out;

    float *qpre, *kpre, *vpre, *gate, *ba, *Wba, *on;
    cudaGetSymbolAddress((void**)&qpre, g_qpre);
    cudaGetSymbolAddress((void**)&kpre, g_kpre);
    cudaGetSymbolAddress((void**)&vpre, g_vpre);
    cudaGetSymbolAddress((void**)&gate, g_gate);
    cudaGetSymbolAddress((void**)&ba,   g_ba);
    cudaGetSymbolAddress((void**)&Wba,  g_Wba);
    cudaGetSymbolAddress((void**)&on,   g_on);

    const int M = Bsz * Tn;   // 8192

    concat_ba_kernel<<<(Dm + 255) / 256, 256>>>(Wb, Wa);

    {
        dim3 blk(256);
        dim3 gq((QKC + BN - 1) / BN, M / BM);
        gemm_kernel<<<gq, blk>>>(x, Wq, qpre, M, QKC, Dm);
        gemm_kernel<<<gq, blk>>>(x, Wk, kpre, M, QKC, Dm);
        dim3 gv((VC + BN - 1) / BN, M / BM);
        gemm_kernel<<<gv, blk>>>(x, Wv, vpre, M, VC, Dm);
        gemm_kernel<<<gv, blk>>>(x, Wg, gate, M, VC, Dm);
        dim3 gb(1, M / BM);
        gemm_kernel<<<gb, blk>>>(x, Wba, ba, M, 16, Dm);
    }

    {
        float *qn, *kn;
        cudaGetSymbolAddress((void**)&qn, g_qn);
        cudaGetSymbolAddress((void**)&kn, g_kn);
        convnorm_qk_kernel<<<Bsz * Tn * Hh, DK>>>(qpre, conv_q, qn, 0.08838834764831845f);
        convnorm_qk_kernel<<<Bsz * Tn * Hh, DK>>>(kpre, conv_k, kn, 1.0f);
        convsilu_v_kernel<<<8192, 256>>>(vpre, conv_v);
        betag_kernel<<<(Bsz * Tn * Hh + 255) / 256, 256>>>(A_log, dt_bias);
    }

    {
        dim3 grid(BH, DV / DVT);
        delta_kernel<<<grid, DVT * 4>>>();
    }

    gatednorm_kernel<<<Bsz * Tn * Hh, DV>>>(gnw);

    {
        dim3 blk(256);
        dim3 go((Dm + BN - 1) / BN, M / BM);
        gemm_kernel<<<go, blk>>>(on, Wo, out, M, Dm, Dm);
    }
}

// round 2
// speedup vs baseline: 2.2048x; 2.2048x over previous
#include <cuda_runtime.h>
#include <cuda_bf16.h>
#include <math.h>

// Problem constants
#define Bsz 2
#define Tn 4096
#define Dm 2048
#define Hh 8
#define DK 128
#define DV 256
#define Wc 4
#define BH (Bsz*Hh)          // 16
#define QKC (Hh*DK)          // 1024
#define VC  (Hh*DV)          // 2048
#define NPRE 6144            // packed q|k|v|g columns

// ---------------- scratch (device globals; no allocations allowed) -------------
__device__ float g_pre [(size_t)Bsz*Tn*NPRE];   // packed projections
__device__ float g_Wcat[(size_t)Dm*NPRE];       // packed weights
__device__ float g_qn  [(size_t)BH*Tn*DK];
__device__ float g_kn  [(size_t)BH*Tn*DK];
__device__ float g_vc  [(size_t)BH*Tn*DV];
__device__ float g_eg  [(size_t)BH*Tn];
__device__ float g_beta[(size_t)BH*Tn];
__device__ float g_o   [(size_t)BH*Tn*DV];
__device__ float g_on  [(size_t)Bsz*Tn*VC];

__device__ __forceinline__ float siluf(float x) { return x / (1.f + __expf(-x)); }

__device__ __forceinline__ unsigned f2tf32(float f) {
    unsigned u;
    asm("cvt.rna.tf32.f32 %0, %1;" : "=r"(u) : "f"(f));
    return u;
}

// ---------------- tf32 tensor-core GEMM: C[M,N] = A[M,K] @ B[K,N] --------------
// Requires M%128==0, N%128==0, K%32==0. 256 threads.
#define GBM 128
#define GBN 128
#define GBK 32
#define SAS 136
#define SBS 136

__global__ void __launch_bounds__(256, 1) gemm_tf32(
    const float* __restrict__ Ag, const float* __restrict__ Bg,
    float* __restrict__ C, int M, int N, int K) {
    __shared__ unsigned sA[GBK * SAS];   // [k][m] transposed
    __shared__ unsigned sB[GBK * SBS];   // [k][n]

    const int tid = threadIdx.x;
    const int lane = tid & 31, wid = tid >> 5;
    const int wm = (wid & 3) * 32;       // warp m-offset (4 warps in m)
    const int wn = (wid >> 2) * 64;      // warp n-offset (2 warps in n)
    const int row0 = blockIdx.y * GBM;
    const int col0 = blockIdx.x * GBN;

    float acc[2][8][4];
#pragma unroll
    for (int mt = 0; mt < 2; mt++)
#pragma unroll
        for (int nt = 0; nt < 8; nt++)
#pragma unroll
            for (int i = 0; i < 4; i++) acc[mt][nt][i] = 0.f;

    float4 ra[4], rb[4];

    // prologue: load tile k0=0 into regs
#pragma unroll
    for (int i = 0; i < 4; i++) {
        int linear = tid + i * 256;
        int m = linear >> 3, k4 = linear & 7;
        ra[i] = *reinterpret_cast<const float4*>(Ag + (size_t)(row0 + m) * K + k4 * 4);
        int kk = linear >> 5, n4 = linear & 31;
        rb[i] = *reinterpret_cast<const float4*>(Bg + (size_t)kk * N + col0 + n4 * 4);
    }

    for (int k0 = 0; k0 < K; k0 += GBK) {
        __syncthreads();
        // STS staged regs (with tf32 conversion)
#pragma unroll
        for (int i = 0; i < 4; i++) {
            int linear = tid + i * 256;
            int m = linear >> 3, k4 = linear & 7;
            const float* rv = reinterpret_cast<const float*>(&ra[i]);
#pragma unroll
            for (int j = 0; j < 4; j++) {
                int jr = (j + k4) & 3;
                sA[(k4 * 4 + jr) * SAS + m] = f2tf32(rv[jr]);
            }
            int kk = linear >> 5, n4 = linear & 31;
            uint4 u;
            u.x = f2tf32(rb[i].x); u.y = f2tf32(rb[i].y);
            u.z = f2tf32(rb[i].z); u.w = f2tf32(rb[i].w);
            *reinterpret_cast<uint4*>(&sB[kk * SBS + n4 * 4]) = u;
        }
        __syncthreads();

        // prefetch next tile
        if (k0 + GBK < K) {
            int kn0 = k0 + GBK;
#pragma unroll
            for (int i = 0; i < 4; i++) {
                int linear = tid + i * 256;
                int m = linear >> 3, k4 = linear & 7;
                ra[i] = *reinterpret_cast<const float4*>(Ag + (size_t)(row0 + m) * K + kn0 + k4 * 4);
                int kk = linear >> 5, n4 = linear & 31;
                rb[i] = *reinterpret_cast<const float4*>(Bg + (size_t)(kn0 + kk) * N + col0 + n4 * 4);
            }
        }

        // compute 4 k-steps of 8
#pragma unroll
        for (int ks = 0; ks < 4; ks++) {
            int krow = ks * 8 + (lane & 3);
            unsigned afr[2][4], bfr[8][2];
#pragma unroll
            for (int mt = 0; mt < 2; mt++) {
                int m0 = wm + mt * 16 + (lane >> 2);
                afr[mt][0] = sA[krow * SAS + m0];
                afr[mt][1] = sA[krow * SAS + m0 + 8];
                afr[mt][2] = sA[(krow + 4) * SAS + m0];
                afr[mt][3] = sA[(krow + 4) * SAS + m0 + 8];
            }
#pragma unroll
            for (int nt = 0; nt < 8; nt++) {
                int n0 = wn + nt * 8 + (lane >> 2);
                bfr[nt][0] = sB[krow * SBS + n0];
                bfr[nt][1] = sB[(krow + 4) * SBS + n0];
            }
#pragma unroll
            for (int mt = 0; mt < 2; mt++)
#pragma unroll
                for (int nt = 0; nt < 8; nt++) {
                    asm volatile(
                        "mma.sync.aligned.m16n8k8.row.col.f32.tf32.tf32.f32 "
                        "{%0,%1,%2,%3}, {%4,%5,%6,%7}, {%8,%9}, {%0,%1,%2,%3};"
                        : "+f"(acc[mt][nt][0]), "+f"(acc[mt][nt][1]),
                          "+f"(acc[mt][nt][2]), "+f"(acc[mt][nt][3])
                        : "r"(afr[mt][0]), "r"(afr[mt][1]), "r"(afr[mt][2]), "r"(afr[mt][3]),
                          "r"(bfr[nt][0]), "r"(bfr[nt][1]));
                }
        }
    }

    // epilogue
#pragma unroll
    for (int mt = 0; mt < 2; mt++) {
#pragma unroll
        for (int nt = 0; nt < 8; nt++) {
            int row = row0 + wm + mt * 16 + (lane >> 2);
            int col = col0 + wn + nt * 8 + (lane & 3) * 2;
            float2 lo = make_float2(acc[mt][nt][0], acc[mt][nt][1]);
            float2 hi = make_float2(acc[mt][nt][2], acc[mt][nt][3]);
            *reinterpret_cast<float2*>(&C[(size_t)row * N + col]) = lo;
            *reinterpret_cast<float2*>(&C[(size_t)(row + 8) * N + col]) = hi;
        }
    }
}

// ---------------- pack Wq|Wk|Wv|Wg -> [Dm][6144] -------------------------------
__global__ void concat_w_kernel(const float* __restrict__ Wq, const float* __restrict__ Wk,
                                const float* __restrict__ Wv, const float* __restrict__ Wg) {
    size_t n = (size_t)Dm * NPRE;
    for (size_t i = (size_t)blockIdx.x * blockDim.x + threadIdx.x; i < n;
         i += (size_t)gridDim.x * blockDim.x) {
        int col = (int)(i % NPRE);
        int k = (int)(i / NPRE);
        float v;
        if (col < 1024)       v = Wq[(size_t)k * 1024 + col];
        else if (col < 2048)  v = Wk[(size_t)k * 1024 + (col - 1024)];
        else if (col < 4096)  v = Wv[(size_t)k * 2048 + (col - 2048)];
        else                  v = Wg[(size_t)k * 2048 + (col - 4096)];
        g_Wcat[i] = v;
    }
}

// ---------------- fused beta/g projection + activations ------------------------
// block 256 = 8 warps; warp w handles row bt = blockIdx.x*8 + w
__global__ void betag_fused_kernel(const float* __restrict__ x,
                                   const float* __restrict__ Wb, const float* __restrict__ Wa,
                                   const float* __restrict__ A_log,
                                   const float* __restrict__ dt_bias) {
    int wid = threadIdx.x >> 5, lane = threadIdx.x & 31;
    int row = blockIdx.x * 8 + wid;
    if (row >= Bsz * Tn) return;
    const float* xr = x + (size_t)row * Dm;
    float accB[8], accA[8];
#pragma unroll
    for (int h = 0; h < 8; h++) { accB[h] = 0.f; accA[h] = 0.f; }
    for (int k = lane; k < Dm; k += 32) {
        float xv = xr[k];
        const float4* wb = reinterpret_cast<const float4*>(Wb + (size_t)k * 8);
        const float4* wa = reinterpret_cast<const float4*>(Wa + (size_t)k * 8);
        float4 b0 = wb[0], b1 = wb[1], a0 = wa[0], a1 = wa[1];
        accB[0] += xv * b0.x; accB[1] += xv * b0.y; accB[2] += xv * b0.z; accB[3] += xv * b0.w;
        accB[4] += xv * b1.x; accB[5] += xv * b1.y; accB[6] += xv * b1.z; accB[7] += xv * b1.w;
        accA[0] += xv * a0.x; accA[1] += xv * a0.y; accA[2] += xv * a0.z; accA[3] += xv * a0.w;
        accA[4] += xv * a1.x; accA[5] += xv * a1.y; accA[6] += xv * a1.z; accA[7] += xv * a1.w;
    }
#pragma unroll
    for (int h = 0; h < 8; h++) {
#pragma unroll
        for (int m = 16; m; m >>= 1) {
            accB[h] += __shfl_xor_sync(0xffffffffu, accB[h], m);
            accA[h] += __shfl_xor_sync(0xffffffffu, accA[h], m);
        }
    }
    if (lane < 8) {
        int h = lane;
        float beta = 1.f / (1.f + expf(-accB[h]));
        float xg = accA[h] + dt_bias[h];
        float sp = (xg > 20.f) ? xg : log1pf(expf(xg));
        float gg = -expf(A_log[h]) * sp;
        int b = row / Tn, t = row % Tn;
        size_t o = (size_t)(b * Hh + h) * Tn + t;
        g_eg[o] = expf(gg);
        g_beta[o] = beta;
    }
}

// ---------------- causal dwconv + silu + l2norm for q/k ------------------------
// pre rows at stride NPRE with column offset `off`; out: [BH][T][128]
__global__ void convnorm_qk_kernel(const float* __restrict__ convw,
                                   float* __restrict__ out, int off, float scale) {
    int idx = blockIdx.x;                 // (b*T + t)*H + h
    int h = idx % Hh;
    int t = (idx / Hh) % Tn;
    int b = idx / (Hh * Tn);
    int c = h * DK + threadIdx.x;         // 128 threads

    const float* base = g_pre + (size_t)b * Tn * NPRE + off;
    float acc = 0.f;
#pragma unroll
    for (int i = 0; i < Wc; i++) {
        int tt = t - (Wc - 1) + i;
        if (tt >= 0) acc += base[(size_t)tt * NPRE + c] * convw[(size_t)c * Wc + i];
    }
    float s = siluf(acc);
    float ss = s * s;
#pragma unroll
    for (int m = 16; m; m >>= 1) ss += __shfl_xor_sync(0xffffffffu, ss, m);
    __shared__ float wsum[4];
    if ((threadIdx.x & 31) == 0) wsum[threadIdx.x >> 5] = ss;
    __syncthreads();
    float tot = wsum[0] + wsum[1] + wsum[2] + wsum[3];
    float r = rsqrtf(tot + 1e-6f) * scale;
    out[(((size_t)(b * Hh + h) * Tn) + t) * DK + threadIdx.x] = s * r;
}

// ---------------- causal dwconv + silu for v -----------------------------------
__global__ void convsilu_v_kernel(const float* __restrict__ convw) {
    size_t total = (size_t)Bsz * Tn * VC;
    for (size_t idx = (size_t)blockIdx.x * blockDim.x + threadIdx.x;
         idx < total; idx += (size_t)gridDim.x * blockDim.x) {
        int c = idx % VC;
        int t = (idx / VC) % Tn;
        int b = idx / ((size_t)VC * Tn);
        int h = c / DV, dv = c % DV;
        const float* base = g_pre + (size_t)b * Tn * NPRE + 2048;
        float acc = 0.f;
#pragma unroll
        for (int i = 0; i < Wc; i++) {
            int tt = t - (Wc - 1) + i;
            if (tt >= 0) acc += base[(size_t)tt * NPRE + c] * convw[(size_t)c * Wc + i];
        }
        g_vc[(((size_t)(b * Hh + h) * Tn) + t) * DV + dv] = siluf(acc);
    }
}

// ---------------- gated delta-rule recurrence ----------------------------------
#define DVT 32
#define STAGE 32
#define SUBW 36

__global__ void __launch_bounds__(DVT*4, 1) delta_kernel() {
    int bh = blockIdx.x;
    int vt = blockIdx.y;
    int tid = threadIdx.x;           // 128
    int col = tid >> 2;
    int sub = tid & 3;
    int gcol = vt * DVT + col;

    const float* kb  = g_kn   + (size_t)bh * Tn * DK;
    const float* qb  = g_qn   + (size_t)bh * Tn * DK;
    const float* vb  = g_vc   + (size_t)bh * Tn * DV;
    const float* egb = g_eg   + (size_t)bh * Tn;
    const float* btb = g_beta + (size_t)bh * Tn;
    float* ob        = g_o    + (size_t)bh * Tn * DV;

    __shared__ float sK[STAGE][4 * SUBW];
    __shared__ float sQ[STAGE][4 * SUBW];
    __shared__ float sV[STAGE][DVT];
    __shared__ float sEg[STAGE];
    __shared__ float sBt[STAGE];

    float S[32];
#pragma unroll
    for (int i = 0; i < 32; i++) S[i] = 0.f;

    for (int c0 = 0; c0 < Tn; c0 += STAGE) {
        __syncthreads();
#pragma unroll
        for (int l = 0; l < 8; l++) {
            int linear = tid + l * 128;
            int tl = linear >> 5;
            int v4 = linear & 31;
            float4 kv = reinterpret_cast<const float4*>(kb + (size_t)(c0 + tl) * DK)[v4];
            float4 qv = reinterpret_cast<const float4*>(qb + (size_t)(c0 + tl) * DK)[v4];
            int off = (v4 >> 3) * SUBW + (v4 & 7) * 4;
            *reinterpret_cast<float4*>(&sK[tl][off]) = kv;
            *reinterpret_cast<float4*>(&sQ[tl][off]) = qv;
        }
#pragma unroll
        for (int l = 0; l < 2; l++) {
            int linear = tid + l * 128;
            int tl = linear >> 3;
            int v4 = linear & 7;
            float4 vv = reinterpret_cast<const float4*>(vb + (size_t)(c0 + tl) * DV + vt * DVT)[v4];
            *reinterpret_cast<float4*>(&sV[tl][v4 * 4]) = vv;
        }
        if (tid < STAGE) {
            sEg[tid] = egb[c0 + tid];
            sBt[tid] = btb[c0 + tid];
        }
        __syncthreads();

        for (int s = 0; s < STAGE; s++) {
            float eg = sEg[s];
            const float4* kr = reinterpret_cast<const float4*>(&sK[s][sub * SUBW]);
            const float4* qr = reinterpret_cast<const float4*>(&sQ[s][sub * SUBW]);

            float4 kq[8];
#pragma unroll
            for (int j = 0; j < 8; j++) kq[j] = kr[j];

            float p0 = 0.f, p1 = 0.f, p2 = 0.f, p3 = 0.f;
#pragma unroll
            for (int j = 0; j < 8; j++) {
                p0 += kq[j].x * S[4 * j + 0];
                p1 += kq[j].y * S[4 * j + 1];
                p2 += kq[j].z * S[4 * j + 2];
                p3 += kq[j].w * S[4 * j + 3];
            }
            float p = (p0 + p1) + (p2 + p3);
            p += __shfl_xor_sync(0xffffffffu, p, 1);
            p += __shfl_xor_sync(0xffffffffu, p, 2);

            float w = sBt[s] * (sV[s][col] - eg * p);

            float o0 = 0.f, o1 = 0.f, o2 = 0.f, o3 = 0.f;
#pragma unroll
            for (int j = 0; j < 8; j++) {
                float4 qv = qr[j];
                S[4 * j + 0] = eg * S[4 * j + 0] + kq[j].x * w;
                S[4 * j + 1] = eg * S[4 * j + 1] + kq[j].y * w;
                S[4 * j + 2] = eg * S[4 * j + 2] + kq[j].z * w;
                S[4 * j + 3] = eg * S[4 * j + 3] + kq[j].w * w;
                o0 += qv.x * S[4 * j + 0];
                o1 += qv.y * S[4 * j + 1];
                o2 += qv.z * S[4 * j + 2];
                o3 += qv.w * S[4 * j + 3];
            }
            float o = (o0 + o1) + (o2 + o3);
            o += __shfl_xor_sync(0xffffffffu, o, 1);
            o += __shfl_xor_sync(0xffffffffu, o, 2);
            if (sub == 0) ob[(size_t)(c0 + s) * DV + gcol] = o;
        }
    }
}

// ---------------- gated RMSNorm + silu(gate) -----------------------------------
__global__ void gatednorm_kernel(const float* __restrict__ g_norm_w) {
    int idx = blockIdx.x;                 // (b*T + t)*H + h
    int h = idx % Hh;
    int t = (idx / Hh) % Tn;
    int b = idx / (Hh * Tn);
    int dv = threadIdx.x;                 // 256
    size_t obase = ((size_t)(b * Hh + h) * Tn + t) * DV;
    float o = g_o[obase + dv];
    float ss = o * o;
#pragma unroll
    for (int m = 16; m; m >>= 1) ss += __shfl_xor_sync(0xffffffffu, ss, m);
    __shared__ float wsum[8];
    if ((threadIdx.x & 31) == 0) wsum[threadIdx.x >> 5] = ss;
    __syncthreads();
    float tot = 0.f;
#pragma unroll
    for (int i = 0; i < 8; i++) tot += wsum[i];
    float r = rsqrtf(tot * (1.f / DV) + 1e-5f);
    float gt = g_pre[((size_t)(b * Tn + t)) * NPRE + 4096 + h * DV + dv];
    g_on[((size_t)(b * Tn + t)) * VC + h * DV + dv] = o * r * g_norm_w[dv] * siluf(gt);
}

// ---------------- launch --------------------------------------------------------
extern "C" void kernel_launch(void* const* d_in, const int* in_sizes, int n_in,
                              void* d_out, int out_size) {
    const float* x       = (const float*)d_in[0];
    const float* Wq      = (const float*)d_in[1];
    const float* Wk      = (const float*)d_in[2];
    const float* Wv      = (const float*)d_in[3];
    const float* Wb      = (const float*)d_in[4];
    const float* Wa      = (const float*)d_in[5];
    const float* Wg      = (const float*)d_in[6];
    const float* Wo      = (const float*)d_in[7];
    const float* conv_q  = (const float*)d_in[8];
    const float* conv_k  = (const float*)d_in[9];
    const float* conv_v  = (const float*)d_in[10];
    const float* A_log   = (const float*)d_in[11];
    const float* dt_bias = (const float*)d_in[12];
    const float* gnw     = (const float*)d_in[13];
    float* out = (float*)d_out;

    float *pre, *Wcat, *on, *qn, *kn;
    cudaGetSymbolAddress((void**)&pre,  g_pre);
    cudaGetSymbolAddress((void**)&Wcat, g_Wcat);
    cudaGetSymbolAddress((void**)&on,   g_on);
    cudaGetSymbolAddress((void**)&qn,   g_qn);
    cudaGetSymbolAddress((void**)&kn,   g_kn);

    const int M = Bsz * Tn;   // 8192

    concat_w_kernel<<<1024, 256>>>(Wq, Wk, Wv, Wg);

    {
        dim3 grid(NPRE / GBN, M / GBM);     // 48 x 64
        gemm_tf32<<<grid, 256>>>(x, Wcat, pre, M, NPRE, Dm);
    }

    betag_fused_kernel<<<M / 8, 256>>>(x, Wb, Wa, A_log, dt_bias);

    convnorm_qk_kernel<<<Bsz * Tn * Hh, DK>>>(conv_q, qn, 0, 0.08838834764831845f);
    convnorm_qk_kernel<<<Bsz * Tn * Hh, DK>>>(conv_k, kn, 1024, 1.0f);
    convsilu_v_kernel<<<8192, 256>>>(conv_v);

    {
        dim3 grid(BH, DV / DVT);
        delta_kernel<<<grid, DVT * 4>>>();
    }

    gatednorm_kernel<<<Bsz * Tn * Hh, DV>>>(gnw);

    {
        dim3 grid(Dm / GBN, M / GBM);       // 16 x 64
        gemm_tf32<<<grid, 256>>>(on, Wo, out, M, Dm, Dm);
    }
}

// round 4
// speedup vs baseline: 3.0757x; 1.3950x over previous
#include <cuda_runtime.h>
#include <cuda_bf16.h>
#include <math.h>
#include <stdint.h>

// Problem constants
#define Bsz 2
#define Tn 4096
#define Dm 2048
#define Hh 8
#define DK 128
#define DV 256
#define Wc 4
#define BH (Bsz*Hh)          // 16
#define QKC (Hh*DK)          // 1024
#define VC  (Hh*DV)          // 2048
#define NPRE 6144            // packed q|k|v|g columns

// ---------------- scratch (device globals; no allocations allowed) -------------
__device__ float g_pre [(size_t)Bsz*Tn*NPRE];   // packed projections
__device__ float g_Wcat[(size_t)Dm*NPRE];       // packed weights [K][N], tf32-rounded
__device__ float g_Wor [(size_t)Dm*Dm];         // Wo [K][N], tf32-rounded
__device__ float g_xr  [(size_t)Bsz*Tn*Dm];     // x rounded to tf32
__device__ float g_qn  [(size_t)BH*Tn*DK];
__device__ float g_kn  [(size_t)BH*Tn*DK];
__device__ float g_vc  [(size_t)BH*Tn*DV];
__device__ float g_eg  [(size_t)BH*Tn];
__device__ float g_beta[(size_t)BH*Tn];
__device__ float g_o   [(size_t)BH*Tn*DV];
__device__ float g_on  [(size_t)Bsz*Tn*VC];     // tf32-rounded

__device__ __forceinline__ float siluf(float x) { return x / (1.f + __expf(-x)); }

__device__ __forceinline__ float tf32r(float f) {
    unsigned u;
    asm("cvt.rna.tf32.f32 %0, %1;" : "=r"(u) : "f"(f));
    return __uint_as_float(u);
}

__device__ __forceinline__ uint32_t smem_u32(const void* p) {
    uint32_t a;
    asm("{ .reg .u64 t; cvta.to.shared.u64 t, %1; cvt.u32.u64 %0, t; }" : "=r"(a) : "l"(p));
    return a;
}

#define CP_ASYNC16(dst, src) \
    asm volatile("cp.async.cg.shared.global [%0], [%1], 16;" \
        :: "r"((uint32_t)(dst)), "l"(src) : "memory")
#define CP_COMMIT() asm volatile("cp.async.commit_group;" ::: "memory")

// ============ mma.sync tf32 GEMM with cp.async pipeline ========================
// C[M,N] = A[M,K] @ B[K,N]. A,B pre-rounded to tf32. M%128==0, N%128==0, K%32==0.
#define TM 128
#define TN 128
#define TKc 32
#define AST 36      // A smem row stride (floats), [m][k]
#define BST 136     // B smem row stride (floats), [k][n]
#define STG_FLOATS (TM*AST + TKc*BST)     // 4608 + 4352 = 8960
#define NST 3
#define SMEM_GEMM (NST*STG_FLOATS*4)      // 107520 bytes

__global__ void __launch_bounds__(256) gemm_mma(
    const float* __restrict__ A, const float* __restrict__ B,
    float* __restrict__ C, int Mtot, int Ntot, int Ktot) {
    extern __shared__ float sm[];
    const int tid = threadIdx.x, lane = tid & 31, wid = tid >> 5;
    const int wm = (wid & 3) * 32;      // 4 warps in m
    const int wn = (wid >> 2) * 64;     // 2 warps in n
    const int m0 = blockIdx.y * TM, n0 = blockIdx.x * TN;
    const int la3 = lane & 3, l4 = lane >> 2;

    float acc[2][8][4];
#pragma unroll
    for (int mt = 0; mt < 2; mt++)
#pragma unroll
        for (int nt = 0; nt < 8; nt++)
#pragma unroll
            for (int i = 0; i < 4; i++) acc[mt][nt][i] = 0.f;

    const int nch = Ktot / TKc;

    auto load_stage = [&](int c, int s) {
        float* sa = sm + s * STG_FLOATS;
        float* sb = sa + TM * AST;
        const float* Ab = A + (size_t)m0 * Ktot + c * TKc;
        const float* Bb = B + (size_t)(c * TKc) * Ntot + n0;
#pragma unroll
        for (int i = 0; i < 4; i++) {           // A: 128 rows x 8 16B-chunks
            int idx = tid + i * 256;
            int r = idx >> 3, cc = idx & 7;
            CP_ASYNC16(smem_u32(sa + r * AST + cc * 4), Ab + (size_t)r * Ktot + cc * 4);
        }
#pragma unroll
        for (int i = 0; i < 4; i++) {           // B: 32 rows x 32 16B-chunks
            int idx = tid + i * 256;
            int r = idx >> 5, n4 = idx & 31;
            CP_ASYNC16(smem_u32(sb + r * BST + n4 * 4), Bb + (size_t)r * Ntot + n4 * 4);
        }
        CP_COMMIT();
    };

    load_stage(0, 0);
    load_stage(1, 1);

    for (int c = 0; c < nch; c++) {
        if (c + 1 < nch) asm volatile("cp.async.wait_group 1;" ::: "memory");
        else             asm volatile("cp.async.wait_group 0;" ::: "memory");
        __syncthreads();
        if (c + 2 < nch) load_stage(c + 2, (c + 2) % NST);

        const float* sa = sm + (c % NST) * STG_FLOATS;
        const float* sb = sa + TM * AST;
#pragma unroll
        for (int ks = 0; ks < 4; ks++) {
            int kb = ks * 8 + la3;
            float a[2][4];
#pragma unroll
            for (int mt = 0; mt < 2; mt++) {
                int mm = wm + mt * 16 + l4;
                a[mt][0] = sa[mm * AST + kb];
                a[mt][1] = sa[(mm + 8) * AST + kb];
                a[mt][2] = sa[mm * AST + kb + 4];
                a[mt][3] = sa[(mm + 8) * AST + kb + 4];
            }
            float b[8][2];
#pragma unroll
            for (int nt = 0; nt < 8; nt++) {
                int nn = wn + nt * 8 + l4;
                b[nt][0] = sb[kb * BST + nn];
                b[nt][1] = sb[(kb + 4) * BST + nn];
            }
#pragma unroll
            for (int mt = 0; mt < 2; mt++)
#pragma unroll
                for (int nt = 0; nt < 8; nt++) {
                    asm volatile(
                        "mma.sync.aligned.m16n8k8.row.col.f32.tf32.tf32.f32 "
                        "{%0,%1,%2,%3}, {%4,%5,%6,%7}, {%8,%9}, {%0,%1,%2,%3};"
                        : "+f"(acc[mt][nt][0]), "+f"(acc[mt][nt][1]),
                          "+f"(acc[mt][nt][2]), "+f"(acc[mt][nt][3])
                        : "r"(__float_as_uint(a[mt][0])), "r"(__float_as_uint(a[mt][1])),
                          "r"(__float_as_uint(a[mt][2])), "r"(__float_as_uint(a[mt][3])),
                          "r"(__float_as_uint(b[nt][0])), "r"(__float_as_uint(b[nt][1])));
                }
        }
    }

    // epilogue
#pragma unroll
    for (int mt = 0; mt < 2; mt++) {
#pragma unroll
        for (int nt = 0; nt < 8; nt++) {
            int row = m0 + wm + mt * 16 + l4;
            int col = n0 + wn + nt * 8 + la3 * 2;
            *reinterpret_cast<float2*>(&C[(size_t)row * Ntot + col]) =
                make_float2(acc[mt][nt][0], acc[mt][nt][1]);
            *reinterpret_cast<float2*>(&C[(size_t)(row + 8) * Ntot + col]) =
                make_float2(acc[mt][nt][2], acc[mt][nt][3]);
        }
    }
}

// ---------------- pack Wq|Wk|Wv|Wg -> g_Wcat[K][6144] (tf32-rounded) ------------
__global__ void concat_w_kernel(const float* __restrict__ Wq, const float* __restrict__ Wk,
                                const float* __restrict__ Wv, const float* __restrict__ Wg) {
    size_t n = (size_t)Dm * NPRE;
    for (size_t i = (size_t)blockIdx.x * blockDim.x + threadIdx.x; i < n;
         i += (size_t)gridDim.x * blockDim.x) {
        int col = (int)(i % NPRE);
        int k = (int)(i / NPRE);
        float v;
        if (col < 1024)       v = Wq[(size_t)k * 1024 + col];
        else if (col < 2048)  v = Wk[(size_t)k * 1024 + (col - 1024)];
        else if (col < 4096)  v = Wv[(size_t)k * 2048 + (col - 2048)];
        else                  v = Wg[(size_t)k * 2048 + (col - 4096)];
        g_Wcat[i] = tf32r(v);
    }
}

// ---------------- round Wo / x to tf32 ------------------------------------------
__global__ void round_wo_kernel(const float* __restrict__ Wo) {
    size_t n = (size_t)Dm * Dm / 4;
    for (size_t i = (size_t)blockIdx.x * blockDim.x + threadIdx.x; i < n;
         i += (size_t)gridDim.x * blockDim.x) {
        float4 v = reinterpret_cast<const float4*>(Wo)[i];
        v.x = tf32r(v.x); v.y = tf32r(v.y); v.z = tf32r(v.z); v.w = tf32r(v.w);
        reinterpret_cast<float4*>(g_Wor)[i] = v;
    }
}
__global__ void round_x_kernel(const float* __restrict__ x) {
    size_t n = (size_t)Bsz * Tn * Dm / 4;
    for (size_t i = (size_t)blockIdx.x * blockDim.x + threadIdx.x; i < n;
         i += (size_t)gridDim.x * blockDim.x) {
        float4 v = reinterpret_cast<const float4*>(x)[i];
        v.x = tf32r(v.x); v.y = tf32r(v.y); v.z = tf32r(v.z); v.w = tf32r(v.w);
        reinterpret_cast<float4*>(g_xr)[i] = v;
    }
}

// ---------------- fused beta/g projection + activations ------------------------
__global__ void betag_fused_kernel(const float* __restrict__ x,
                                   const float* __restrict__ Wb, const float* __restrict__ Wa,
                                   const float* __restrict__ A_log,
                                   const float* __restrict__ dt_bias) {
    int wid = threadIdx.x >> 5, lane = threadIdx.x & 31;
    int row = blockIdx.x * 8 + wid;
    if (row >= Bsz * Tn) return;
    const float* xr = x + (size_t)row * Dm;
    float accB[8], accA[8];
#pragma unroll
    for (int h = 0; h < 8; h++) { accB[h] = 0.f; accA[h] = 0.f; }
    for (int k = lane; k < Dm; k += 32) {
        float xv = xr[k];
        const float4* wb = reinterpret_cast<const float4*>(Wb + (size_t)k * 8);
        const float4* wa = reinterpret_cast<const float4*>(Wa + (size_t)k * 8);
        float4 b0 = wb[0], b1 = wb[1], a0 = wa[0], a1 = wa[1];
        accB[0] += xv * b0.x; accB[1] += xv * b0.y; accB[2] += xv * b0.z; accB[3] += xv * b0.w;
        accB[4] += xv * b1.x; accB[5] += xv * b1.y; accB[6] += xv * b1.z; accB[7] += xv * b1.w;
        accA[0] += xv * a0.x; accA[1] += xv * a0.y; accA[2] += xv * a0.z; accA[3] += xv * a0.w;
        accA[4] += xv * a1.x; accA[5] += xv * a1.y; accA[6] += xv * a1.z; accA[7] += xv * a1.w;
    }
#pragma unroll
    for (int h = 0; h < 8; h++) {
#pragma unroll
        for (int m = 16; m; m >>= 1) {
            accB[h] += __shfl_xor_sync(0xffffffffu, accB[h], m);
            accA[h] += __shfl_xor_sync(0xffffffffu, accA[h], m);
        }
    }
    if (lane < 8) {
        int h = lane;
        float beta = 1.f / (1.f + expf(-accB[h]));
        float xg = accA[h] + dt_bias[h];
        float sp = (xg > 20.f) ? xg : log1pf(expf(xg));
        float gg = -expf(A_log[h]) * sp;
        int b = row / Tn, t = row % Tn;
        size_t o = (size_t)(b * Hh + h) * Tn + t;
        g_eg[o] = expf(gg);
        g_beta[o] = beta;
    }
}

// ---------------- causal dwconv + silu + l2norm for q/k ------------------------
__global__ void convnorm_qk_kernel(const float* __restrict__ convw,
                                   float* __restrict__ out, int off, float scale) {
    int idx = blockIdx.x;
    int h = idx % Hh;
    int t = (idx / Hh) % Tn;
    int b = idx / (Hh * Tn);
    int c = h * DK + threadIdx.x;

    const float* base = g_pre + (size_t)b * Tn * NPRE + off;
    float acc = 0.f;
#pragma unroll
    for (int i = 0; i < Wc; i++) {
        int tt = t - (Wc - 1) + i;
        if (tt >= 0) acc += base[(size_t)tt * NPRE + c] * convw[(size_t)c * Wc + i];
    }
    float s = siluf(acc);
    float ss = s * s;
#pragma unroll
    for (int m = 16; m; m >>= 1) ss += __shfl_xor_sync(0xffffffffu, ss, m);
    __shared__ float wsum[4];
    if ((threadIdx.x & 31) == 0) wsum[threadIdx.x >> 5] = ss;
    __syncthreads();
    float tot = wsum[0] + wsum[1] + wsum[2] + wsum[3];
    float r = rsqrtf(tot + 1e-6f) * scale;
    out[(((size_t)(b * Hh + h) * Tn) + t) * DK + threadIdx.x] = s * r;
}

// ---------------- causal dwconv + silu for v -----------------------------------
__global__ void convsilu_v_kernel(const float* __restrict__ convw) {
    size_t total = (size_t)Bsz * Tn * VC;
    for (size_t idx = (size_t)blockIdx.x * blockDim.x + threadIdx.x;
         idx < total; idx += (size_t)gridDim.x * blockDim.x) {
        int c = idx % VC;
        int t = (idx / VC) % Tn;
        int b = idx / ((size_t)VC * Tn);
        int h = c / DV, dv = c % DV;
        const float* base = g_pre + (size_t)b * Tn * NPRE + 2048;
        float acc = 0.f;
#pragma unroll
        for (int i = 0; i < Wc; i++) {
            int tt = t - (Wc - 1) + i;
            if (tt >= 0) acc += base[(size_t)tt * NPRE + c] * convw[(size_t)c * Wc + i];
        }
        g_vc[(((size_t)(b * Hh + h) * Tn) + t) * DV + dv] = siluf(acc);
    }
}

// ---------------- gated delta-rule recurrence ----------------------------------
#define DVT 32
#define STAGE 32
#define SUBW 36

__global__ void __launch_bounds__(DVT*4, 1) delta_kernel() {
    int bh = blockIdx.x;
    int vt = blockIdx.y;
    int tid = threadIdx.x;
    int col = tid >> 2;
    int sub = tid & 3;
    int gcol = vt * DVT + col;

    const float* kb  = g_kn   + (size_t)bh * Tn * DK;
    const float* qb  = g_qn   + (size_t)bh * Tn * DK;
    const float* vb  = g_vc   + (size_t)bh * Tn * DV;
    const float* egb = g_eg   + (size_t)bh * Tn;
    const float* btb = g_beta + (size_t)bh * Tn;
    float* ob        = g_o    + (size_t)bh * Tn * DV;

    __shared__ float sK[STAGE][4 * SUBW];
    __shared__ float sQ[STAGE][4 * SUBW];
    __shared__ float sV[STAGE][DVT];
    __shared__ float sEg[STAGE];
    __shared__ float sBt[STAGE];

    float S[32];
#pragma unroll
    for (int i = 0; i < 32; i++) S[i] = 0.f;

    for (int c0 = 0; c0 < Tn; c0 += STAGE) {
        __syncthreads();
#pragma unroll
        for (int l = 0; l < 8; l++) {
            int linear = tid + l * 128;
            int tl = linear >> 5;
            int v4 = linear & 31;
            float4 kv = reinterpret_cast<const float4*>(kb + (size_t)(c0 + tl) * DK)[v4];
            float4 qv = reinterpret_cast<const float4*>(qb + (size_t)(c0 + tl) * DK)[v4];
            int off = (v4 >> 3) * SUBW + (v4 & 7) * 4;
            *reinterpret_cast<float4*>(&sK[tl][off]) = kv;
            *reinterpret_cast<float4*>(&sQ[tl][off]) = qv;
        }
#pragma unroll
        for (int l = 0; l < 2; l++) {
            int linear = tid + l * 128;
            int tl = linear >> 3;
            int v4 = linear & 7;
            float4 vv = reinterpret_cast<const float4*>(vb + (size_t)(c0 + tl) * DV + vt * DVT)[v4];
            *reinterpret_cast<float4*>(&sV[tl][v4 * 4]) = vv;
        }
        if (tid < STAGE) {
            sEg[tid] = egb[c0 + tid];
            sBt[tid] = btb[c0 + tid];
        }
        __syncthreads();

        for (int s = 0; s < STAGE; s++) {
            float eg = sEg[s];
            const float4* kr = reinterpret_cast<const float4*>(&sK[s][sub * SUBW]);
            const float4* qr = reinterpret_cast<const float4*>(&sQ[s][sub * SUBW]);

            float4 kq[8];
#pragma unroll
            for (int j = 0; j < 8; j++) kq[j] = kr[j];

            float p0 = 0.f, p1 = 0.f, p2 = 0.f, p3 = 0.f;
#pragma unroll
            for (int j = 0; j < 8; j++) {
                p0 += kq[j].x * S[4 * j + 0];
                p1 += kq[j].y * S[4 * j + 1];
                p2 += kq[j].z * S[4 * j + 2];
                p3 += kq[j].w * S[4 * j + 3];
            }
            float p = (p0 + p1) + (p2 + p3);
            p += __shfl_xor_sync(0xffffffffu, p, 1);
            p += __shfl_xor_sync(0xffffffffu, p, 2);

            float w = sBt[s] * (sV[s][col] - eg * p);

            float o0 = 0.f, o1 = 0.f, o2 = 0.f, o3 = 0.f;
#pragma unroll
            for (int j = 0; j < 8; j++) {
                float4 qv = qr[j];
                S[4 * j + 0] = eg * S[4 * j + 0] + kq[j].x * w;
                S[4 * j + 1] = eg * S[4 * j + 1] + kq[j].y * w;
                S[4 * j + 2] = eg * S[4 * j + 2] + kq[j].z * w;
                S[4 * j + 3] = eg * S[4 * j + 3] + kq[j].w * w;
                o0 += qv.x * S[4 * j + 0];
                o1 += qv.y * S[4 * j + 1];
                o2 += qv.z * S[4 * j + 2];
                o3 += qv.w * S[4 * j + 3];
            }
            float o = (o0 + o1) + (o2 + o3);
            o += __shfl_xor_sync(0xffffffffu, o, 1);
            o += __shfl_xor_sync(0xffffffffu, o, 2);
            if (sub == 0) ob[(size_t)(c0 + s) * DV + gcol] = o;
        }
    }
}

// ---------------- gated RMSNorm + silu(gate), tf32-rounded output ---------------
__global__ void gatednorm_kernel(const float* __restrict__ g_norm_w) {
    int idx = blockIdx.x;
    int h = idx % Hh;
    int t = (idx / Hh) % Tn;
    int b = idx / (Hh * Tn);
    int dv = threadIdx.x;
    size_t obase = ((size_t)(b * Hh + h) * Tn + t) * DV;
    float o = g_o[obase + dv];
    float ss = o * o;
#pragma unroll
    for (int m = 16; m; m >>= 1) ss += __shfl_xor_sync(0xffffffffu, ss, m);
    __shared__ float wsum[8];
    if ((threadIdx.x & 31) == 0) wsum[threadIdx.x >> 5] = ss;
    __syncthreads();
    float tot = 0.f;
#pragma unroll
    for (int i = 0; i < 8; i++) tot += wsum[i];
    float r = rsqrtf(tot * (1.f / DV) + 1e-5f);
    float gt = g_pre[((size_t)(b * Tn + t)) * NPRE + 4096 + h * DV + dv];
    g_on[((size_t)(b * Tn + t)) * VC + h * DV + dv] =
        tf32r(o * r * g_norm_w[dv] * siluf(gt));
}

// ---------------- launch --------------------------------------------------------
extern "C" void kernel_launch(void* const* d_in, const int* in_sizes, int n_in,
                              void* d_out, int out_size) {
    const float* x       = (const float*)d_in[0];
    const float* Wq      = (const float*)d_in[1];
    const float* Wk      = (const float*)d_in[2];
    const float* Wv      = (const float*)d_in[3];
    const float* Wb      = (const float*)d_in[4];
    const float* Wa      = (const float*)d_in[5];
    const float* Wg      = (const float*)d_in[6];
    const float* Wo      = (const float*)d_in[7];
    const float* conv_q  = (const float*)d_in[8];
    const float* conv_k  = (const float*)d_in[9];
    const float* conv_v  = (const float*)d_in[10];
    const float* A_log   = (const float*)d_in[11];
    const float* dt_bias = (const float*)d_in[12];
    const float* gnw     = (const float*)d_in[13];
    float* out = (float*)d_out;

    float *pre, *Wcat, *Wor, *xr, *on, *qn, *kn;
    cudaGetSymbolAddress((void**)&pre,  g_pre);
    cudaGetSymbolAddress((void**)&Wcat, g_Wcat);
    cudaGetSymbolAddress((void**)&Wor,  g_Wor);
    cudaGetSymbolAddress((void**)&xr,   g_xr);
    cudaGetSymbolAddress((void**)&on,   g_on);
    cudaGetSymbolAddress((void**)&qn,   g_qn);
    cudaGetSymbolAddress((void**)&kn,   g_kn);

    cudaFuncSetAttribute(gemm_mma, cudaFuncAttributeMaxDynamicSharedMemorySize, SMEM_GEMM);

    const int M = Bsz * Tn;   // 8192

    concat_w_kernel<<<1024, 256>>>(Wq, Wk, Wv, Wg);
    round_wo_kernel<<<512, 256>>>(Wo);
    round_x_kernel<<<1024, 256>>>(x);

    // big projection GEMM: pre[8192,6144] = xr @ Wcat
    gemm_mma<<<dim3(NPRE / TN, M / TM), 256, SMEM_GEMM>>>(xr, Wcat, pre, M, NPRE, Dm);

    betag_fused_kernel<<<M / 8, 256>>>(x, Wb, Wa, A_log, dt_bias);

    convnorm_qk_kernel<<<Bsz * Tn * Hh, DK>>>(conv_q, qn, 0, 0.08838834764831845f);
    convnorm_qk_kernel<<<Bsz * Tn * Hh, DK>>>(conv_k, kn, 1024, 1.0f);
    convsilu_v_kernel<<<8192, 256>>>(conv_v);

    {
        dim3 grid(BH, DV / DVT);
        delta_kernel<<<grid, DVT * 4>>>();
    }

    gatednorm_kernel<<<Bsz * Tn * Hh, DV>>>(gnw);

    // output GEMM: out[8192,2048] = on @ Wor
    gemm_mma<<<dim3(Dm / TN, M / TM), 256, SMEM_GEMM>>>(on, Wor, out, M, Dm, Dm);
}

// round 5
// speedup vs baseline: 3.1084x; 1.0106x over previous
#include <cuda_runtime.h>
#include <cuda_bf16.h>
#include <math.h>
#include <stdint.h>

// Problem constants
#define Bsz 2
#define Tn 4096
#define Dm 2048
#define Hh 8
#define DK 128
#define DV 256
#define Wc 4
#define BH (Bsz*Hh)          // 16
#define QKC (Hh*DK)          // 1024
#define VC  (Hh*DV)          // 2048
#define NPRE 6144            // packed q|k|v|g columns

// ---------------- scratch (device globals; no allocations allowed) -------------
__device__ float g_pre [(size_t)Bsz*Tn*NPRE];   // packed projections
__device__ float g_Wcat[(size_t)Dm*NPRE];       // packed weights [K][N], tf32-rounded
__device__ float g_Wor [(size_t)Dm*Dm];         // Wo [K][N], tf32-rounded
__device__ float g_xr  [(size_t)Bsz*Tn*Dm];     // x rounded to tf32
__device__ float g_qn  [(size_t)BH*Tn*DK];
__device__ float g_kn  [(size_t)BH*Tn*DK];
__device__ float g_vc  [(size_t)BH*Tn*DV];
__device__ float g_eg  [(size_t)BH*Tn];
__device__ float g_beta[(size_t)BH*Tn];
__device__ float g_o   [(size_t)BH*Tn*DV];
__device__ float g_on  [(size_t)Bsz*Tn*VC];     // tf32-rounded

__device__ __forceinline__ float siluf(float x) { return x / (1.f + __expf(-x)); }

__device__ __forceinline__ float tf32r(float f) {
    unsigned u;
    asm("cvt.rna.tf32.f32 %0, %1;" : "=r"(u) : "f"(f));
    return __uint_as_float(u);
}

__device__ __forceinline__ uint32_t smem_u32(const void* p) {
    uint32_t a;
    asm("{ .reg .u64 t; cvta.to.shared.u64 t, %1; cvt.u32.u64 %0, t; }" : "=r"(a) : "l"(p));
    return a;
}

#define CP_ASYNC16(dst, src) \
    asm volatile("cp.async.cg.shared.global [%0], [%1], 16;" \
        :: "r"((uint32_t)(dst)), "l"(src) : "memory")
#define CP_COMMIT() asm volatile("cp.async.commit_group;" ::: "memory")

// ============ mma.sync tf32 GEMM, 4 warps, 64x64 warp tiles ====================
// C[M,N] = A[M,K] @ B[K,N]. A,B pre-rounded to tf32. M%128==0, N%128==0, K%32==0.
#define TM 128
#define TN 128
#define TKc 32
#define AST 36      // A smem row stride (floats), [m][k]
#define BST 136     // B smem row stride (floats), [k][n]
#define STG_FLOATS (TM*AST + TKc*BST)     // 4608 + 4352 = 8960
#define NST 3
#define SMEM_GEMM (NST*STG_FLOATS*4)      // 107520 bytes

__global__ void __launch_bounds__(128, 2) gemm_mma(
    const float* __restrict__ A, const float* __restrict__ B,
    float* __restrict__ C, int Mtot, int Ntot, int Ktot) {
    extern __shared__ float sm[];
    const int tid = threadIdx.x, lane = tid & 31, wid = tid >> 5;
    const int wm = (wid & 1) * 64;      // 2 warps in m
    const int wn = (wid >> 1) * 64;     // 2 warps in n
    const int m0 = blockIdx.y * TM, n0 = blockIdx.x * TN;
    const int la3 = lane & 3, l4 = lane >> 2;

    float acc[4][8][4];
#pragma unroll
    for (int mt = 0; mt < 4; mt++)
#pragma unroll
        for (int nt = 0; nt < 8; nt++)
#pragma unroll
            for (int i = 0; i < 4; i++) acc[mt][nt][i] = 0.f;

    const int nch = Ktot / TKc;

    auto load_stage = [&](int c, int s) {
        float* sa = sm + s * STG_FLOATS;
        float* sb = sa + TM * AST;
        const float* Ab = A + (size_t)m0 * Ktot + c * TKc;
        const float* Bb = B + (size_t)(c * TKc) * Ntot + n0;
#pragma unroll
        for (int i = 0; i < 8; i++) {           // A: 128 rows x 8 16B-chunks
            int idx = tid + i * 128;
            int r = idx >> 3, cc = idx & 7;
            CP_ASYNC16(smem_u32(sa + r * AST + cc * 4), Ab + (size_t)r * Ktot + cc * 4);
        }
#pragma unroll
        for (int i = 0; i < 8; i++) {           // B: 32 rows x 32 16B-chunks
            int idx = tid + i * 128;
            int r = idx >> 5, n4 = idx & 31;
            CP_ASYNC16(smem_u32(sb + r * BST + n4 * 4), Bb + (size_t)r * Ntot + n4 * 4);
        }
        CP_COMMIT();
    };

    load_stage(0, 0);
    load_stage(1, 1);

    for (int c = 0; c < nch; c++) {
        if (c + 1 < nch) asm volatile("cp.async.wait_group 1;" ::: "memory");
        else             asm volatile("cp.async.wait_group 0;" ::: "memory");
        __syncthreads();
        if (c + 2 < nch) load_stage(c + 2, (c + 2) % NST);

        const float* sa = sm + (c % NST) * STG_FLOATS;
        const float* sb = sa + TM * AST;
#pragma unroll
        for (int ks = 0; ks < 4; ks++) {
            int kb = ks * 8 + la3;
            float a[4][4];
#pragma unroll
            for (int mt = 0; mt < 4; mt++) {
                int mm = wm + mt * 16 + l4;
                a[mt][0] = sa[mm * AST + kb];
                a[mt][1] = sa[(mm + 8) * AST + kb];
                a[mt][2] = sa[mm * AST + kb + 4];
                a[mt][3] = sa[(mm + 8) * AST + kb + 4];
            }
            float b[8][2];
#pragma unroll
            for (int nt = 0; nt < 8; nt++) {
                int nn = wn + nt * 8 + l4;
                b[nt][0] = sb[kb * BST + nn];
                b[nt][1] = sb[(kb + 4) * BST + nn];
            }
#pragma unroll
            for (int mt = 0; mt < 4; mt++)
#pragma unroll
                for (int nt = 0; nt < 8; nt++) {
                    asm volatile(
                        "mma.sync.aligned.m16n8k8.row.col.f32.tf32.tf32.f32 "
                        "{%0,%1,%2,%3}, {%4,%5,%6,%7}, {%8,%9}, {%0,%1,%2,%3};"
                        : "+f"(acc[mt][nt][0]), "+f"(acc[mt][nt][1]),
                          "+f"(acc[mt][nt][2]), "+f"(acc[mt][nt][3])
                        : "r"(__float_as_uint(a[mt][0])), "r"(__float_as_uint(a[mt][1])),
                          "r"(__float_as_uint(a[mt][2])), "r"(__float_as_uint(a[mt][3])),
                          "r"(__float_as_uint(b[nt][0])), "r"(__float_as_uint(b[nt][1])));
                }
        }
    }

    // epilogue
#pragma unroll
    for (int mt = 0; mt < 4; mt++) {
#pragma unroll
        for (int nt = 0; nt < 8; nt++) {
            int row = m0 + wm + mt * 16 + l4;
            int col = n0 + wn + nt * 8 + la3 * 2;
            *reinterpret_cast<float2*>(&C[(size_t)row * Ntot + col]) =
                make_float2(acc[mt][nt][0], acc[mt][nt][1]);
            *reinterpret_cast<float2*>(&C[(size_t)(row + 8) * Ntot + col]) =
                make_float2(acc[mt][nt][2], acc[mt][nt][3]);
        }
    }
}

// ---------------- pack Wq|Wk|Wv|Wg -> g_Wcat[K][6144] (tf32-rounded) ------------
__global__ void concat_w_kernel(const float* __restrict__ Wq, const float* __restrict__ Wk,
                                const float* __restrict__ Wv, const float* __restrict__ Wg) {
    size_t n = (size_t)Dm * NPRE;
    for (size_t i = (size_t)blockIdx.x * blockDim.x + threadIdx.x; i < n;
         i += (size_t)gridDim.x * blockDim.x) {
        int col = (int)(i % NPRE);
        int k = (int)(i / NPRE);
        float v;
        if (col < 1024)       v = Wq[(size_t)k * 1024 + col];
        else if (col < 2048)  v = Wk[(size_t)k * 1024 + (col - 1024)];
        else if (col < 4096)  v = Wv[(size_t)k * 2048 + (col - 2048)];
        else                  v = Wg[(size_t)k * 2048 + (col - 4096)];
        g_Wcat[i] = tf32r(v);
    }
}

// ---------------- round Wo / x to tf32 ------------------------------------------
__global__ void round_wo_kernel(const float* __restrict__ Wo) {
    size_t n = (size_t)Dm * Dm / 4;
    for (size_t i = (size_t)blockIdx.x * blockDim.x + threadIdx.x; i < n;
         i += (size_t)gridDim.x * blockDim.x) {
        float4 v = reinterpret_cast<const float4*>(Wo)[i];
        v.x = tf32r(v.x); v.y = tf32r(v.y); v.z = tf32r(v.z); v.w = tf32r(v.w);
        reinterpret_cast<float4*>(g_Wor)[i] = v;
    }
}
__global__ void round_x_kernel(const float* __restrict__ x) {
    size_t n = (size_t)Bsz * Tn * Dm / 4;
    for (size_t i = (size_t)blockIdx.x * blockDim.x + threadIdx.x; i < n;
         i += (size_t)gridDim.x * blockDim.x) {
        float4 v = reinterpret_cast<const float4*>(x)[i];
        v.x = tf32r(v.x); v.y = tf32r(v.y); v.z = tf32r(v.z); v.w = tf32r(v.w);
        reinterpret_cast<float4*>(g_xr)[i] = v;
    }
}

// ---------------- fused beta/g projection + activations ------------------------
__global__ void betag_fused_kernel(const float* __restrict__ x,
                                   const float* __restrict__ Wb, const float* __restrict__ Wa,
                                   const float* __restrict__ A_log,
                                   const float* __restrict__ dt_bias) {
    int wid = threadIdx.x >> 5, lane = threadIdx.x & 31;
    int row = blockIdx.x * 8 + wid;
    if (row >= Bsz * Tn) return;
    const float* xr = x + (size_t)row * Dm;
    float accB[8], accA[8];
#pragma unroll
    for (int h = 0; h < 8; h++) { accB[h] = 0.f; accA[h] = 0.f; }
    for (int k = lane; k < Dm; k += 32) {
        float xv = xr[k];
        const float4* wb = reinterpret_cast<const float4*>(Wb + (size_t)k * 8);
        const float4* wa = reinterpret_cast<const float4*>(Wa + (size_t)k * 8);
        float4 b0 = wb[0], b1 = wb[1], a0 = wa[0], a1 = wa[1];
        accB[0] += xv * b0.x; accB[1] += xv * b0.y; accB[2] += xv * b0.z; accB[3] += xv * b0.w;
        accB[4] += xv * b1.x; accB[5] += xv * b1.y; accB[6] += xv * b1.z; accB[7] += xv * b1.w;
        accA[0] += xv * a0.x; accA[1] += xv * a0.y; accA[2] += xv * a0.z; accA[3] += xv * a0.w;
        accA[4] += xv * a1.x; accA[5] += xv * a1.y; accA[6] += xv * a1.z; accA[7] += xv * a1.w;
    }
#pragma unroll
    for (int h = 0; h < 8; h++) {
#pragma unroll
        for (int m = 16; m; m >>= 1) {
            accB[h] += __shfl_xor_sync(0xffffffffu, accB[h], m);
            accA[h] += __shfl_xor_sync(0xffffffffu, accA[h], m);
        }
    }
    if (lane < 8) {
        int h = lane;
        float beta = 1.f / (1.f + expf(-accB[h]));
        float xg = accA[h] + dt_bias[h];
        float sp = (xg > 20.f) ? xg : log1pf(expf(xg));
        float gg = -expf(A_log[h]) * sp;
        int b = row / Tn, t = row % Tn;
        size_t o = (size_t)(b * Hh + h) * Tn + t;
        g_eg[o] = expf(gg);
        g_beta[o] = beta;
    }
}

// ---------------- causal dwconv + silu + l2norm for q/k ------------------------
__global__ void convnorm_qk_kernel(const float* __restrict__ convw,
                                   float* __restrict__ out, int off, float scale) {
    int idx = blockIdx.x;
    int h = idx % Hh;
    int t = (idx / Hh) % Tn;
    int b = idx / (Hh * Tn);
    int c = h * DK + threadIdx.x;

    const float* base = g_pre + (size_t)b * Tn * NPRE + off;
    float acc = 0.f;
#pragma unroll
    for (int i = 0; i < Wc; i++) {
        int tt = t - (Wc - 1) + i;
        if (tt >= 0) acc += base[(size_t)tt * NPRE + c] * convw[(size_t)c * Wc + i];
    }
    float s = siluf(acc);
    float ss = s * s;
#pragma unroll
    for (int m = 16; m; m >>= 1) ss += __shfl_xor_sync(0xffffffffu, ss, m);
    __shared__ float wsum[4];
    if ((threadIdx.x & 31) == 0) wsum[threadIdx.x >> 5] = ss;
    __syncthreads();
    float tot = wsum[0] + wsum[1] + wsum[2] + wsum[3];
    float r = rsqrtf(tot + 1e-6f) * scale;
    out[(((size_t)(b * Hh + h) * Tn) + t) * DK + threadIdx.x] = s * r;
}

// ---------------- causal dwconv + silu for v -----------------------------------
__global__ void convsilu_v_kernel(const float* __restrict__ convw) {
    size_t total = (size_t)Bsz * Tn * VC;
    for (size_t idx = (size_t)blockIdx.x * blockDim.x + threadIdx.x;
         idx < total; idx += (size_t)gridDim.x * blockDim.x) {
        int c = idx % VC;
        int t = (idx / VC) % Tn;
        int b = idx / ((size_t)VC * Tn);
        int h = c / DV, dv = c % DV;
        const float* base = g_pre + (size_t)b * Tn * NPRE + 2048;
        float acc = 0.f;
#pragma unroll
        for (int i = 0; i < Wc; i++) {
            int tt = t - (Wc - 1) + i;
            if (tt >= 0) acc += base[(size_t)tt * NPRE + c] * convw[(size_t)c * Wc + i];
        }
        g_vc[(((size_t)(b * Hh + h) * Tn) + t) * DV + dv] = siluf(acc);
    }
}

// ---------------- gated delta-rule recurrence ----------------------------------
#define DVT 32
#define STAGE 32
#define SUBW 36

__global__ void __launch_bounds__(DVT*4, 1) delta_kernel() {
    int bh = blockIdx.x;
    int vt = blockIdx.y;
    int tid = threadIdx.x;
    int col = tid >> 2;
    int sub = tid & 3;
    int gcol = vt * DVT + col;

    const float* kb  = g_kn   + (size_t)bh * Tn * DK;
    const float* qb  = g_qn   + (size_t)bh * Tn * DK;
    const float* vb  = g_vc   + (size_t)bh * Tn * DV;
    const float* egb = g_eg   + (size_t)bh * Tn;
    const float* btb = g_beta + (size_t)bh * Tn;
    float* ob        = g_o    + (size_t)bh * Tn * DV;

    __shared__ float sK[STAGE][4 * SUBW];
    __shared__ float sQ[STAGE][4 * SUBW];
    __shared__ float sV[STAGE][DVT];
    __shared__ float sEg[STAGE];
    __shared__ float sBt[STAGE];

    float S[32];
#pragma unroll
    for (int i = 0; i < 32; i++) S[i] = 0.f;

    for (int c0 = 0; c0 < Tn; c0 += STAGE) {
        __syncthreads();
#pragma unroll
        for (int l = 0; l < 8; l++) {
            int linear = tid + l * 128;
            int tl = linear >> 5;
            int v4 = linear & 31;
            float4 kv = reinterpret_cast<const float4*>(kb + (size_t)(c0 + tl) * DK)[v4];
            float4 qv = reinterpret_cast<const float4*>(qb + (size_t)(c0 + tl) * DK)[v4];
            int off = (v4 >> 3) * SUBW + (v4 & 7) * 4;
            *reinterpret_cast<float4*>(&sK[tl][off]) = kv;
            *reinterpret_cast<float4*>(&sQ[tl][off]) = qv;
        }
#pragma unroll
        for (int l = 0; l < 2; l++) {
            int linear = tid + l * 128;
            int tl = linear >> 3;
            int v4 = linear & 7;
            float4 vv = reinterpret_cast<const float4*>(vb + (size_t)(c0 + tl) * DV + vt * DVT)[v4];
            *reinterpret_cast<float4*>(&sV[tl][v4 * 4]) = vv;
        }
        if (tid < STAGE) {
            sEg[tid] = egb[c0 + tid];
            sBt[tid] = btb[c0 + tid];
        }
        __syncthreads();

        for (int s = 0; s < STAGE; s++) {
            float eg = sEg[s];
            const float4* kr = reinterpret_cast<const float4*>(&sK[s][sub * SUBW]);
            const float4* qr = reinterpret_cast<const float4*>(&sQ[s][sub * SUBW]);

            float4 kq[8];
#pragma unroll
            for (int j = 0; j < 8; j++) kq[j] = kr[j];

            float p0 = 0.f, p1 = 0.f, p2 = 0.f, p3 = 0.f;
#pragma unroll
            for (int j = 0; j < 8; j++) {
                p0 += kq[j].x * S[4 * j + 0];
                p1 += kq[j].y * S[4 * j + 1];
                p2 += kq[j].z * S[4 * j + 2];
                p3 += kq[j].w * S[4 * j + 3];
            }
            float p = (p0 + p1) + (p2 + p3);
            p += __shfl_xor_sync(0xffffffffu, p, 1);
            p += __shfl_xor_sync(0xffffffffu, p, 2);

            float w = sBt[s] * (sV[s][col] - eg * p);

            float o0 = 0.f, o1 = 0.f, o2 = 0.f, o3 = 0.f;
#pragma unroll
            for (int j = 0; j < 8; j++) {
                float4 qv = qr[j];
                S[4 * j + 0] = eg * S[4 * j + 0] + kq[j].x * w;
                S[4 * j + 1] = eg * S[4 * j + 1] + kq[j].y * w;
                S[4 * j + 2] = eg * S[4 * j + 2] + kq[j].z * w;
                S[4 * j + 3] = eg * S[4 * j + 3] + kq[j].w * w;
                o0 += qv.x * S[4 * j + 0];
                o1 += qv.y * S[4 * j + 1];
                o2 += qv.z * S[4 * j + 2];
                o3 += qv.w * S[4 * j + 3];
            }
            float o = (o0 + o1) + (o2 + o3);
            o += __shfl_xor_sync(0xffffffffu, o, 1);
            o += __shfl_xor_sync(0xffffffffu, o, 2);
            if (sub == 0) ob[(size_t)(c0 + s) * DV + gcol] = o;
        }
    }
}

// ---------------- gated RMSNorm + silu(gate), tf32-rounded output ---------------
__global__ void gatednorm_kernel(const float* __restrict__ g_norm_w) {
    int idx = blockIdx.x;
    int h = idx % Hh;
    int t = (idx / Hh) % Tn;
    int b = idx / (Hh * Tn);
    int dv = threadIdx.x;
    size_t obase = ((size_t)(b * Hh + h) * Tn + t) * DV;
    float o = g_o[obase + dv];
    float ss = o * o;
#pragma unroll
    for (int m = 16; m; m >>= 1) ss += __shfl_xor_sync(0xffffffffu, ss, m);
    __shared__ float wsum[8];
    if ((threadIdx.x & 31) == 0) wsum[threadIdx.x >> 5] = ss;
    __syncthreads();
    float tot = 0.f;
#pragma unroll
    for (int i = 0; i < 8; i++) tot += wsum[i];
    float r = rsqrtf(tot * (1.f / DV) + 1e-5f);
    float gt = g_pre[((size_t)(b * Tn + t)) * NPRE + 4096 + h * DV + dv];
    g_on[((size_t)(b * Tn + t)) * VC + h * DV + dv] =
        tf32r(o * r * g_norm_w[dv] * siluf(gt));
}

// ---------------- launch --------------------------------------------------------
extern "C" void kernel_launch(void* const* d_in, const int* in_sizes, int n_in,
                              void* d_out, int out_size) {
    const float* x       = (const float*)d_in[0];
    const float* Wq      = (const float*)d_in[1];
    const float* Wk      = (const float*)d_in[2];
    const float* Wv      = (const float*)d_in[3];
    const float* Wb      = (const float*)d_in[4];
    const float* Wa      = (const float*)d_in[5];
    const float* Wg      = (const float*)d_in[6];
    const float* Wo      = (const float*)d_in[7];
    const float* conv_q  = (const float*)d_in[8];
    const float* conv_k  = (const float*)d_in[9];
    const float* conv_v  = (const float*)d_in[10];
    const float* A_log   = (const float*)d_in[11];
    const float* dt_bias = (const float*)d_in[12];
    const float* gnw     = (const float*)d_in[13];
    float* out = (float*)d_out;

    float *pre, *Wcat, *Wor, *xr, *on, *qn, *kn;
    cudaGetSymbolAddress((void**)&pre,  g_pre);
    cudaGetSymbolAddress((void**)&Wcat, g_Wcat);
    cudaGetSymbolAddress((void**)&Wor,  g_Wor);
    cudaGetSymbolAddress((void**)&xr,   g_xr);
    cudaGetSymbolAddress((void**)&on,   g_on);
    cudaGetSymbolAddress((void**)&qn,   g_qn);
    cudaGetSymbolAddress((void**)&kn,   g_kn);

    cudaFuncSetAttribute(gemm_mma, cudaFuncAttributeMaxDynamicSharedMemorySize, SMEM_GEMM);

    const int M = Bsz * Tn;   // 8192

    concat_w_kernel<<<1024, 256>>>(Wq, Wk, Wv, Wg);
    round_wo_kernel<<<512, 256>>>(Wo);
    round_x_kernel<<<1024, 256>>>(x);

    // big projection GEMM: pre[8192,6144] = xr @ Wcat
    gemm_mma<<<dim3(NPRE / TN, M / TM), 128, SMEM_GEMM>>>(xr, Wcat, pre, M, NPRE, Dm);

    betag_fused_kernel<<<M / 8, 256>>>(x, Wb, Wa, A_log, dt_bias);

    convnorm_qk_kernel<<<Bsz * Tn * Hh, DK>>>(conv_q, qn, 0, 0.08838834764831845f);
    convnorm_qk_kernel<<<Bsz * Tn * Hh, DK>>>(conv_k, kn, 1024, 1.0f);
    convsilu_v_kernel<<<8192, 256>>>(conv_v);

    {
        dim3 grid(BH, DV / DVT);
        delta_kernel<<<grid, DVT * 4>>>();
    }

    gatednorm_kernel<<<Bsz * Tn * Hh, DV>>>(gnw);

    // output GEMM: out[8192,2048] = on @ Wor
    gemm_mma<<<dim3(Dm / TN, M / TM), 128, SMEM_GEMM>>>(on, Wor, out, M, Dm, Dm);
}

// round 6
// speedup vs baseline: 4.2591x; 1.3702x over previous
#include <cuda_runtime.h>
#include <cuda_fp16.h>
#include <math.h>
#include <stdint.h>

// Problem constants
#define Bsz 2
#define Tn 4096
#define Dm 2048
#define Hh 8
#define DK 128
#define DV 256
#define Wc 4
#define BH (Bsz*Hh)          // 16
#define QKC (Hh*DK)          // 1024
#define VC  (Hh*DV)          // 2048
#define NPRE 6144            // packed q|k|v|g columns

// ---------------- scratch (device globals; no allocations allowed) -------------
__device__ float   g_pre [(size_t)Bsz*Tn*NPRE];   // packed projections (fp32)
__device__ __half2 g_Wch [(size_t)(Dm/2)*NPRE];   // packed weights, half2 pairs along K
__device__ __half2 g_Woh [(size_t)(Dm/2)*Dm];     // Wo, half2 pairs along K
__device__ __half2 g_xh  [(size_t)Bsz*Tn*(Dm/2)]; // x, half2 pairs along K
__device__ __half2 g_onh [(size_t)Bsz*Tn*(VC/2)]; // gated-norm output, half2 pairs
__device__ float   g_qn  [(size_t)BH*Tn*DK];
__device__ float   g_kn  [(size_t)BH*Tn*DK];
__device__ float   g_vc  [(size_t)BH*Tn*DV];
__device__ float   g_eg  [(size_t)BH*Tn];
__device__ float   g_beta[(size_t)BH*Tn];
__device__ float   g_o   [(size_t)BH*Tn*DV];

__device__ __forceinline__ float siluf(float x) { return x / (1.f + __expf(-x)); }

__device__ __forceinline__ uint32_t smem_u32(const void* p) {
    uint32_t a;
    asm("{ .reg .u64 t; cvta.to.shared.u64 t, %1; cvt.u32.u64 %0, t; }" : "=r"(a) : "l"(p));
    return a;
}

#define CP_ASYNC16(dst, src) \
    asm volatile("cp.async.cg.shared.global [%0], [%1], 16;" \
        :: "r"((uint32_t)(dst)), "l"(src) : "memory")
#define CP_COMMIT() asm volatile("cp.async.commit_group;" ::: "memory")

// ============ fp16 m16n8k16 GEMM, fp32 accum, cp.async pipeline ================
// C[M,N] = A[M,K] @ B[K,N]. A: [M][K/2] half2 (pairs along K). B: [K/2][N] half2
// (pairs along K). M%128==0, N%128==0, K%32==0.
#define TM 128
#define TN 128
#define TKc2 16      // half2 words of K per chunk (32 k-values)
#define AST2 20      // A smem row stride (words): 16 + 4 pad
#define BST2 136     // B smem row stride (words): 128 + 8 pad
#define STG_WORDS (TM*AST2 + TKc2*BST2)    // 2560 + 2176 = 4736
#define NST 3
#define SMEM_GEMMH (NST*STG_WORDS*4)       // 56832 bytes

__global__ void __launch_bounds__(128, 2) gemm_h(
    const __half2* __restrict__ A, const __half2* __restrict__ B,
    float* __restrict__ C, int Mtot, int Ntot, int K2tot) {
    extern __shared__ uint32_t sm[];
    const int tid = threadIdx.x, lane = tid & 31, wid = tid >> 5;
    const int wm = (wid & 1) * 64;      // 2 warps in m
    const int wn = (wid >> 1) * 64;     // 2 warps in n
    const int m0 = blockIdx.y * TM, n0 = blockIdx.x * TN;
    const int la3 = lane & 3, l4 = lane >> 2;

    float acc[4][8][4];
#pragma unroll
    for (int mt = 0; mt < 4; mt++)
#pragma unroll
        for (int nt = 0; nt < 8; nt++)
#pragma unroll
            for (int i = 0; i < 4; i++) acc[mt][nt][i] = 0.f;

    const int nch = K2tot / TKc2;

    auto load_stage = [&](int c, int s) {
        uint32_t* sa = sm + s * STG_WORDS;
        uint32_t* sb = sa + TM * AST2;
        const __half2* Ab = A + (size_t)m0 * K2tot + c * TKc2;
        const __half2* Bb = B + (size_t)(c * TKc2) * Ntot + n0;
#pragma unroll
        for (int i = 0; i < 4; i++) {           // A: 128 rows x 4 16B-chunks
            int idx = tid + i * 128;
            int r = idx >> 2, cc = idx & 3;
            CP_ASYNC16(smem_u32(sa + r * AST2 + cc * 4), Ab + (size_t)r * K2tot + cc * 4);
        }
#pragma unroll
        for (int i = 0; i < 4; i++) {           // B: 16 rows x 32 16B-chunks
            int idx = tid + i * 128;
            int r = idx >> 5, n4 = idx & 31;
            CP_ASYNC16(smem_u32(sb + r * BST2 + n4 * 4), Bb + (size_t)r * Ntot + n4 * 4);
        }
        CP_COMMIT();
    };

    load_stage(0, 0);
    load_stage(1, 1);

    for (int c = 0; c < nch; c++) {
        if (c + 1 < nch) asm volatile("cp.async.wait_group 1;" ::: "memory");
        else             asm volatile("cp.async.wait_group 0;" ::: "memory");
        __syncthreads();
        if (c + 2 < nch) load_stage(c + 2, (c + 2) % NST);

        const uint32_t* sa = sm + (c % NST) * STG_WORDS;
        const uint32_t* sb = sa + TM * AST2;
#pragma unroll
        for (int ks = 0; ks < 2; ks++) {
            uint32_t a[4][4];
#pragma unroll
            for (int mt = 0; mt < 4; mt++) {
                int mm = wm + mt * 16 + l4;
                int base = mm * AST2 + ks * 8 + la3;
                a[mt][0] = sa[base];
                a[mt][1] = sa[base + 8 * AST2];
                a[mt][2] = sa[base + 4];
                a[mt][3] = sa[base + 8 * AST2 + 4];
            }
            uint32_t b[8][2];
#pragma unroll
            for (int nt = 0; nt < 8; nt++) {
                int nn = wn + nt * 8 + l4;
                b[nt][0] = sb[(ks * 8 + la3) * BST2 + nn];
                b[nt][1] = sb[(ks * 8 + la3 + 4) * BST2 + nn];
            }
#pragma unroll
            for (int mt = 0; mt < 4; mt++)
#pragma unroll
                for (int nt = 0; nt < 8; nt++) {
                    asm volatile(
                        "mma.sync.aligned.m16n8k16.row.col.f32.f16.f16.f32 "
                        "{%0,%1,%2,%3}, {%4,%5,%6,%7}, {%8,%9}, {%0,%1,%2,%3};"
                        : "+f"(acc[mt][nt][0]), "+f"(acc[mt][nt][1]),
                          "+f"(acc[mt][nt][2]), "+f"(acc[mt][nt][3])
                        : "r"(a[mt][0]), "r"(a[mt][1]), "r"(a[mt][2]), "r"(a[mt][3]),
                          "r"(b[nt][0]), "r"(b[nt][1]));
                }
        }
    }

    // epilogue (same C-frag layout as before)
#pragma unroll
    for (int mt = 0; mt < 4; mt++) {
#pragma unroll
        for (int nt = 0; nt < 8; nt++) {
            int row = m0 + wm + mt * 16 + l4;
            int col = n0 + wn + nt * 8 + la3 * 2;
            *reinterpret_cast<float2*>(&C[(size_t)row * Ntot + col]) =
                make_float2(acc[mt][nt][0], acc[mt][nt][1]);
            *reinterpret_cast<float2*>(&C[(size_t)(row + 8) * Ntot + col]) =
                make_float2(acc[mt][nt][2], acc[mt][nt][3]);
        }
    }
}

// ---------------- pack Wq|Wk|Wv|Wg -> g_Wch [K/2][6144] half2 -------------------
__global__ void pack_w_kernel(const float* __restrict__ Wq, const float* __restrict__ Wk,
                              const float* __restrict__ Wv, const float* __restrict__ Wg) {
    size_t n = (size_t)(Dm / 2) * NPRE;
    for (size_t i = (size_t)blockIdx.x * blockDim.x + threadIdx.x; i < n;
         i += (size_t)gridDim.x * blockDim.x) {
        int col = (int)(i % NPRE);
        int k2 = (int)(i / NPRE);
        const float* src; int c;
        if (col < 1024)       { src = Wq; c = col;        }
        else if (col < 2048)  { src = Wk; c = col - 1024; }
        else if (col < 4096)  { src = Wv; c = col - 2048; }
        else                  { src = Wg; c = col - 4096; }
        int ncol = (col < 2048) ? 1024 : 2048;
        float v0 = src[(size_t)(2 * k2) * ncol + c];
        float v1 = src[(size_t)(2 * k2 + 1) * ncol + c];
        g_Wch[i] = __floats2half2_rn(v0, v1);
    }
}

// ---------------- pack Wo -> g_Woh [K/2][2048] half2 ----------------------------
__global__ void pack_wo_kernel(const float* __restrict__ Wo) {
    size_t n = (size_t)(Dm / 2) * Dm;
    for (size_t i = (size_t)blockIdx.x * blockDim.x + threadIdx.x; i < n;
         i += (size_t)gridDim.x * blockDim.x) {
        int col = (int)(i % Dm);
        int k2 = (int)(i / Dm);
        float v0 = Wo[(size_t)(2 * k2) * Dm + col];
        float v1 = Wo[(size_t)(2 * k2 + 1) * Dm + col];
        g_Woh[i] = __floats2half2_rn(v0, v1);
    }
}

// ---------------- pack x -> g_xh [M][K/2] half2 ---------------------------------
__global__ void pack_x_kernel(const float* __restrict__ x) {
    size_t n = (size_t)Bsz * Tn * Dm / 2;
    for (size_t i = (size_t)blockIdx.x * blockDim.x + threadIdx.x; i < n;
         i += (size_t)gridDim.x * blockDim.x) {
        float2 v = reinterpret_cast<const float2*>(x)[i];
        g_xh[i] = __floats2half2_rn(v.x, v.y);
    }
}

// ---------------- fused beta/g projection + activations ------------------------
__global__ void betag_fused_kernel(const float* __restrict__ x,
                                   const float* __restrict__ Wb, const float* __restrict__ Wa,
                                   const float* __restrict__ A_log,
                                   const float* __restrict__ dt_bias) {
    int wid = threadIdx.x >> 5, lane = threadIdx.x & 31;
    int row = blockIdx.x * 8 + wid;
    if (row >= Bsz * Tn) return;
    const float* xr = x + (size_t)row * Dm;
    float accB[8], accA[8];
#pragma unroll
    for (int h = 0; h < 8; h++) { accB[h] = 0.f; accA[h] = 0.f; }
    for (int k = lane; k < Dm; k += 32) {
        float xv = xr[k];
        const float4* wb = reinterpret_cast<const float4*>(Wb + (size_t)k * 8);
        const float4* wa = reinterpret_cast<const float4*>(Wa + (size_t)k * 8);
        float4 b0 = wb[0], b1 = wb[1], a0 = wa[0], a1 = wa[1];
        accB[0] += xv * b0.x; accB[1] += xv * b0.y; accB[2] += xv * b0.z; accB[3] += xv * b0.w;
        accB[4] += xv * b1.x; accB[5] += xv * b1.y; accB[6] += xv * b1.z; accB[7] += xv * b1.w;
        accA[0] += xv * a0.x; accA[1] += xv * a0.y; accA[2] += xv * a0.z; accA[3] += xv * a0.w;
        accA[4] += xv * a1.x; accA[5] += xv * a1.y; accA[6] += xv * a1.z; accA[7] += xv * a1.w;
    }
#pragma unroll
    for (int h = 0; h < 8; h++) {
#pragma unroll
        for (int m = 16; m; m >>= 1) {
            accB[h] += __shfl_xor_sync(0xffffffffu, accB[h], m);
            accA[h] += __shfl_xor_sync(0xffffffffu, accA[h], m);
        }
    }
    if (lane < 8) {
        int h = lane;
        float beta = 1.f / (1.f + expf(-accB[h]));
        float xg = accA[h] + dt_bias[h];
        float sp = (xg > 20.f) ? xg : log1pf(expf(xg));
        float gg = -expf(A_log[h]) * sp;
        int b = row / Tn, t = row % Tn;
        size_t o = (size_t)(b * Hh + h) * Tn + t;
        g_eg[o] = expf(gg);
        g_beta[o] = beta;
    }
}

// ---------------- causal dwconv + silu + l2norm for q/k ------------------------
__global__ void convnorm_qk_kernel(const float* __restrict__ convw,
                                   float* __restrict__ out, int off, float scale) {
    int idx = blockIdx.x;
    int h = idx % Hh;
    int t = (idx / Hh) % Tn;
    int b = idx / (Hh * Tn);
    int c = h * DK + threadIdx.x;

    const float* base = g_pre + (size_t)b * Tn * NPRE + off;
    float acc = 0.f;
#pragma unroll
    for (int i = 0; i < Wc; i++) {
        int tt = t - (Wc - 1) + i;
        if (tt >= 0) acc += base[(size_t)tt * NPRE + c] * convw[(size_t)c * Wc + i];
    }
    float s = siluf(acc);
    float ss = s * s;
#pragma unroll
    for (int m = 16; m; m >>= 1) ss += __shfl_xor_sync(0xffffffffu, ss, m);
    __shared__ float wsum[4];
    if ((threadIdx.x & 31) == 0) wsum[threadIdx.x >> 5] = ss;
    __syncthreads();
    float tot = wsum[0] + wsum[1] + wsum[2] + wsum[3];
    float r = rsqrtf(tot + 1e-6f) * scale;
    out[(((size_t)(b * Hh + h) * Tn) + t) * DK + threadIdx.x] = s * r;
}

// ---------------- causal dwconv + silu for v -----------------------------------
__global__ void convsilu_v_kernel(const float* __restrict__ convw) {
    size_t total = (size_t)Bsz * Tn * VC;
    for (size_t idx = (size_t)blockIdx.x * blockDim.x + threadIdx.x;
         idx < total; idx += (size_t)gridDim.x * blockDim.x) {
        int c = idx % VC;
        int t = (idx / VC) % Tn;
        int b = idx / ((size_t)VC * Tn);
        int h = c / DV, dv = c % DV;
        const float* base = g_pre + (size_t)b * Tn * NPRE + 2048;
        float acc = 0.f;
#pragma unroll
        for (int i = 0; i < Wc; i++) {
            int tt = t - (Wc - 1) + i;
            if (tt >= 0) acc += base[(size_t)tt * NPRE + c] * convw[(size_t)c * Wc + i];
        }
        g_vc[(((size_t)(b * Hh + h) * Tn) + t) * DV + dv] = siluf(acc);
    }
}

// ---------------- gated delta-rule recurrence ----------------------------------
#define DVT 32
#define STAGE 32
#define SUBW 36

__global__ void __launch_bounds__(DVT*4, 1) delta_kernel() {
    int bh = blockIdx.x;
    int vt = blockIdx.y;
    int tid = threadIdx.x;
    int col = tid >> 2;
    int sub = tid & 3;
    int gcol = vt * DVT + col;

    const float* kb  = g_kn   + (size_t)bh * Tn * DK;
    const float* qb  = g_qn   + (size_t)bh * Tn * DK;
    const float* vb  = g_vc   + (size_t)bh * Tn * DV;
    const float* egb = g_eg   + (size_t)bh * Tn;
    const float* btb = g_beta + (size_t)bh * Tn;
    float* ob        = g_o    + (size_t)bh * Tn * DV;

    __shared__ float sK[STAGE][4 * SUBW];
    __shared__ float sQ[STAGE][4 * SUBW];
    __shared__ float sV[STAGE][DVT];
    __shared__ float sEg[STAGE];
    __shared__ float sBt[STAGE];

    float S[32];
#pragma unroll
    for (int i = 0; i < 32; i++) S[i] = 0.f;

    for (int c0 = 0; c0 < Tn; c0 += STAGE) {
        __syncthreads();
#pragma unroll
        for (int l = 0; l < 8; l++) {
            int linear = tid + l * 128;
            int tl = linear >> 5;
            int v4 = linear & 31;
            float4 kv = reinterpret_cast<const float4*>(kb + (size_t)(c0 + tl) * DK)[v4];
            float4 qv = reinterpret_cast<const float4*>(qb + (size_t)(c0 + tl) * DK)[v4];
            int off = (v4 >> 3) * SUBW + (v4 & 7) * 4;
            *reinterpret_cast<float4*>(&sK[tl][off]) = kv;
            *reinterpret_cast<float4*>(&sQ[tl][off]) = qv;
        }
#pragma unroll
        for (int l = 0; l < 2; l++) {
            int linear = tid + l * 128;
            int tl = linear >> 3;
            int v4 = linear & 7;
            float4 vv = reinterpret_cast<const float4*>(vb + (size_t)(c0 + tl) * DV + vt * DVT)[v4];
            *reinterpret_cast<float4*>(&sV[tl][v4 * 4]) = vv;
        }
        if (tid < STAGE) {
            sEg[tid] = egb[c0 + tid];
            sBt[tid] = btb[c0 + tid];
        }
        __syncthreads();

        for (int s = 0; s < STAGE; s++) {
            float eg = sEg[s];
            const float4* kr = reinterpret_cast<const float4*>(&sK[s][sub * SUBW]);
            const float4* qr = reinterpret_cast<const float4*>(&sQ[s][sub * SUBW]);

            float4 kq[8];
#pragma unroll
            for (int j = 0; j < 8; j++) kq[j] = kr[j];

            float p0 = 0.f, p1 = 0.f, p2 = 0.f, p3 = 0.f;
#pragma unroll
            for (int j = 0; j < 8; j++) {
                p0 += kq[j].x * S[4 * j + 0];
                p1 += kq[j].y * S[4 * j + 1];
                p2 += kq[j].z * S[4 * j + 2];
                p3 += kq[j].w * S[4 * j + 3];
            }
            float p = (p0 + p1) + (p2 + p3);
            p += __shfl_xor_sync(0xffffffffu, p, 1);
            p += __shfl_xor_sync(0xffffffffu, p, 2);

            float w = sBt[s] * (sV[s][col] - eg * p);

            float o0 = 0.f, o1 = 0.f, o2 = 0.f, o3 = 0.f;
#pragma unroll
            for (int j = 0; j < 8; j++) {
                float4 qv = qr[j];
                S[4 * j + 0] = eg * S[4 * j + 0] + kq[j].x * w;
                S[4 * j + 1] = eg * S[4 * j + 1] + kq[j].y * w;
                S[4 * j + 2] = eg * S[4 * j + 2] + kq[j].z * w;
                S[4 * j + 3] = eg * S[4 * j + 3] + kq[j].w * w;
                o0 += qv.x * S[4 * j + 0];
                o1 += qv.y * S[4 * j + 1];
                o2 += qv.z * S[4 * j + 2];
                o3 += qv.w * S[4 * j + 3];
            }
            float o = (o0 + o1) + (o2 + o3);
            o += __shfl_xor_sync(0xffffffffu, o, 1);
            o += __shfl_xor_sync(0xffffffffu, o, 2);
            if (sub == 0) ob[(size_t)(c0 + s) * DV + gcol] = o;
        }
    }
}

// ---------------- gated RMSNorm + silu(gate), half2 output ---------------------
// 128 threads, each handles dv = 2*tid, 2*tid+1
__global__ void gatednorm_kernel(const float* __restrict__ g_norm_w) {
    int idx = blockIdx.x;
    int h = idx % Hh;
    int t = (idx / Hh) % Tn;
    int b = idx / (Hh * Tn);
    int dv = threadIdx.x * 2;
    size_t obase = ((size_t)(b * Hh + h) * Tn + t) * DV;
    float o0 = g_o[obase + dv];
    float o1 = g_o[obase + dv + 1];
    float ss = o0 * o0 + o1 * o1;
#pragma unroll
    for (int m = 16; m; m >>= 1) ss += __shfl_xor_sync(0xffffffffu, ss, m);
    __shared__ float wsum[4];
    if ((threadIdx.x & 31) == 0) wsum[threadIdx.x >> 5] = ss;
    __syncthreads();
    float tot = wsum[0] + wsum[1] + wsum[2] + wsum[3];
    float r = rsqrtf(tot * (1.f / DV) + 1e-5f);
    size_t gb = ((size_t)(b * Tn + t)) * NPRE + 4096 + h * DV + dv;
    float gt0 = g_pre[gb], gt1 = g_pre[gb + 1];
    float v0 = o0 * r * g_norm_w[dv] * siluf(gt0);
    float v1 = o1 * r * g_norm_w[dv + 1] * siluf(gt1);
    g_onh[((size_t)(b * Tn + t)) * (VC / 2) + (h * DV + dv) / 2] = __floats2half2_rn(v0, v1);
}

// ---------------- launch --------------------------------------------------------
extern "C" void kernel_launch(void* const* d_in, const int* in_sizes, int n_in,
                              void* d_out, int out_size) {
    const float* x       = (const float*)d_in[0];
    const float* Wq      = (const float*)d_in[1];
    const float* Wk      = (const float*)d_in[2];
    const float* Wv      = (const float*)d_in[3];
    const float* Wb      = (const float*)d_in[4];
    const float* Wa      = (const float*)d_in[5];
    const float* Wg      = (const float*)d_in[6];
    const float* Wo      = (const float*)d_in[7];
    const float* conv_q  = (const float*)d_in[8];
    const float* conv_k  = (const float*)d_in[9];
    const float* conv_v  = (const float*)d_in[10];
    const float* A_log   = (const float*)d_in[11];
    const float* dt_bias = (const float*)d_in[12];
    const float* gnw     = (const float*)d_in[13];
    float* out = (float*)d_out;

    float *pre, *qn, *kn;
    __half2 *Wch, *Woh, *xh, *onh;
    cudaGetSymbolAddress((void**)&pre, g_pre);
    cudaGetSymbolAddress((void**)&Wch, g_Wch);
    cudaGetSymbolAddress((void**)&Woh, g_Woh);
    cudaGetSymbolAddress((void**)&xh,  g_xh);
    cudaGetSymbolAddress((void**)&onh, g_onh);
    cudaGetSymbolAddress((void**)&qn,  g_qn);
    cudaGetSymbolAddress((void**)&kn,  g_kn);

    cudaFuncSetAttribute(gemm_h, cudaFuncAttributeMaxDynamicSharedMemorySize, SMEM_GEMMH);

    const int M = Bsz * Tn;   // 8192

    pack_w_kernel<<<1024, 256>>>(Wq, Wk, Wv, Wg);
    pack_wo_kernel<<<512, 256>>>(Wo);
    pack_x_kernel<<<1024, 256>>>(x);

    // big projection GEMM: pre[8192,6144] = xh @ Wch
    gemm_h<<<dim3(NPRE / TN, M / TM), 128, SMEM_GEMMH>>>(xh, Wch, pre, M, NPRE, Dm / 2);

    betag_fused_kernel<<<M / 8, 256>>>(x, Wb, Wa, A_log, dt_bias);

    convnorm_qk_kernel<<<Bsz * Tn * Hh, DK>>>(conv_q, qn, 0, 0.08838834764831845f);
    convnorm_qk_kernel<<<Bsz * Tn * Hh, DK>>>(conv_k, kn, 1024, 1.0f);
    convsilu_v_kernel<<<8192, 256>>>(conv_v);

    {
        dim3 grid(BH, DV / DVT);
        delta_kernel<<<grid, DVT * 4>>>();
    }

    gatednorm_kernel<<<Bsz * Tn * Hh, DV / 2>>>(gnw);

    // output GEMM: out[8192,2048] = onh @ Woh
    gemm_h<<<dim3(Dm / TN, M / TM), 128, SMEM_GEMMH>>>(onh, Woh, out, M, Dm, Dm / 2);
}

// round 8
// speedup vs baseline: 4.6034x; 1.0808x over previous
#include <cuda_runtime.h>
#include <cuda_fp16.h>
#include <math.h>
#include <stdint.h>

// Problem constants
#define Bsz 2
#define Tn 4096
#define Dm 2048
#define Hh 8
#define DK 128
#define DV 256
#define Wc 4
#define BH (Bsz*Hh)          // 16
#define QKC (Hh*DK)          // 1024
#define VC  (Hh*DV)          // 2048
#define NPRE 6144            // packed q|k|v|g columns

// ---------------- scratch (device globals; no allocations allowed) -------------
__device__ float   g_pre [(size_t)Bsz*Tn*NPRE];   // packed projections (fp32)
__device__ __half2 g_Wch [(size_t)(Dm/2)*NPRE];   // packed weights, half2 pairs along K
__device__ __half2 g_Woh [(size_t)(Dm/2)*Dm];     // Wo, half2 pairs along K
__device__ __half2 g_xh  [(size_t)Bsz*Tn*(Dm/2)]; // x, half2 pairs along K
__device__ __half2 g_onh [(size_t)Bsz*Tn*(VC/2)]; // gated-norm output, half2 pairs
__device__ float   g_qn  [(size_t)BH*Tn*DK];
__device__ float   g_kn  [(size_t)BH*Tn*DK];
__device__ float   g_vc  [(size_t)BH*Tn*DV];
__device__ float   g_eg  [(size_t)BH*Tn];
__device__ float   g_beta[(size_t)BH*Tn];
__device__ float   g_o   [(size_t)BH*Tn*DV];

__device__ __forceinline__ float siluf(float x) { return x / (1.f + __expf(-x)); }

__device__ __forceinline__ uint32_t smem_u32(const void* p) {
    uint32_t a;
    asm("{ .reg .u64 t; cvta.to.shared.u64 t, %1; cvt.u32.u64 %0, t; }" : "=r"(a) : "l"(p));
    return a;
}

#define CP_ASYNC16(dst, src) \
    asm volatile("cp.async.cg.shared.global [%0], [%1], 16;" \
        :: "r"((uint32_t)(dst)), "l"(src) : "memory")
#define CP_COMMIT() asm volatile("cp.async.commit_group;" ::: "memory")

// ============ fp16 m16n8k16 GEMM, fp32 accum, 4-stage cp.async pipeline ========
// C[M,N] = A[M,K] @ B[K,N]. A: [M][K/2] half2 (pairs along K). B: [K/2][N] half2
// (pairs along K). M%128==0, N%128==0, K%32==0.
#define TM 128
#define TN 128
#define TKc2 16      // half2 words of K per chunk (32 k-values)
#define AST2 20      // A smem row stride (words): 16 + 4 pad
#define BST2 136     // B smem row stride (words): 128 + 8 pad
#define STG_WORDS (TM*AST2 + TKc2*BST2)    // 2560 + 2176 = 4736
#define NST 4
#define SMEM_GEMMH (NST*STG_WORDS*4)       // 75776 bytes

__global__ void __launch_bounds__(128, 2) gemm_h(
    const __half2* __restrict__ A, const __half2* __restrict__ B,
    float* __restrict__ C, int Mtot, int Ntot, int K2tot) {
    extern __shared__ uint32_t sm[];
    const int tid = threadIdx.x, lane = tid & 31, wid = tid >> 5;
    const int wm = (wid & 1) * 64;      // 2 warps in m
    const int wn = (wid >> 1) * 64;     // 2 warps in n
    const int m0 = blockIdx.y * TM, n0 = blockIdx.x * TN;
    const int la3 = lane & 3, l4 = lane >> 2;

    float acc[4][8][4];
#pragma unroll
    for (int mt = 0; mt < 4; mt++)
#pragma unroll
        for (int nt = 0; nt < 8; nt++)
#pragma unroll
            for (int i = 0; i < 4; i++) acc[mt][nt][i] = 0.f;

    const int nch = K2tot / TKc2;

    auto load_stage = [&](int c, int s) {
        uint32_t* sa = sm + s * STG_WORDS;
        uint32_t* sb = sa + TM * AST2;
        const __half2* Ab = A + (size_t)m0 * K2tot + c * TKc2;
        const __half2* Bb = B + (size_t)(c * TKc2) * Ntot + n0;
#pragma unroll
        for (int i = 0; i < 4; i++) {           // A: 128 rows x 4 16B-chunks
            int idx = tid + i * 128;
            int r = idx >> 2, cc = idx & 3;
            CP_ASYNC16(smem_u32(sa + r * AST2 + cc * 4), Ab + (size_t)r * K2tot + cc * 4);
        }
#pragma unroll
        for (int i = 0; i < 4; i++) {           // B: 16 rows x 32 16B-chunks
            int idx = tid + i * 128;
            int r = idx >> 5, n4 = idx & 31;
            CP_ASYNC16(smem_u32(sb + r * BST2 + n4 * 4), Bb + (size_t)r * Ntot + n4 * 4);
        }
        CP_COMMIT();
    };

    load_stage(0, 0);
    load_stage(1, 1);
    load_stage(2, 2);

    for (int c = 0; c < nch; c++) {
        if (c + 3 <= nch)      asm volatile("cp.async.wait_group 2;" ::: "memory");
        else if (c + 2 == nch) asm volatile("cp.async.wait_group 1;" ::: "memory");
        else                   asm volatile("cp.async.wait_group 0;" ::: "memory");
        __syncthreads();
        if (c + 3 < nch) load_stage(c + 3, (c + 3) % NST);

        const uint32_t* sa = sm + (c % NST) * STG_WORDS;
        const uint32_t* sb = sa + TM * AST2;
#pragma unroll
        for (int ks = 0; ks < 2; ks++) {
            uint32_t a[4][4];
#pragma unroll
            for (int mt = 0; mt < 4; mt++) {
                int mm = wm + mt * 16 + l4;
                int base = mm * AST2 + ks * 8 + la3;
                a[mt][0] = sa[base];
                a[mt][1] = sa[base + 8 * AST2];
                a[mt][2] = sa[base + 4];
                a[mt][3] = sa[base + 8 * AST2 + 4];
            }
            uint32_t b[8][2];
#pragma unroll
            for (int nt = 0; nt < 8; nt++) {
                int nn = wn + nt * 8 + l4;
                b[nt][0] = sb[(ks * 8 + la3) * BST2 + nn];
                b[nt][1] = sb[(ks * 8 + la3 + 4) * BST2 + nn];
            }
#pragma unroll
            for (int mt = 0; mt < 4; mt++)
#pragma unroll
                for (int nt = 0; nt < 8; nt++) {
                    asm volatile(
                        "mma.sync.aligned.m16n8k16.row.col.f32.f16.f16.f32 "
                        "{%0,%1,%2,%3}, {%4,%5,%6,%7}, {%8,%9}, {%0,%1,%2,%3};"
                        : "+f"(acc[mt][nt][0]), "+f"(acc[mt][nt][1]),
                          "+f"(acc[mt][nt][2]), "+f"(acc[mt][nt][3])
                        : "r"(a[mt][0]), "r"(a[mt][1]), "r"(a[mt][2]), "r"(a[mt][3]),
                          "r"(b[nt][0]), "r"(b[nt][1]));
                }
        }
    }

    // epilogue
#pragma unroll
    for (int mt = 0; mt < 4; mt++) {
#pragma unroll
        for (int nt = 0; nt < 8; nt++) {
            int row = m0 + wm + mt * 16 + l4;
            int col = n0 + wn + nt * 8 + la3 * 2;
            *reinterpret_cast<float2*>(&C[(size_t)row * Ntot + col]) =
                make_float2(acc[mt][nt][0], acc[mt][nt][1]);
            *reinterpret_cast<float2*>(&C[(size_t)(row + 8) * Ntot + col]) =
                make_float2(acc[mt][nt][2], acc[mt][nt][3]);
        }
    }
}

// ---------------- pack Wq|Wk|Wv|Wg -> g_Wch [K/2][6144] half2 -------------------
__global__ void pack_w_kernel(const float* __restrict__ Wq, const float* __restrict__ Wk,
                              const float* __restrict__ Wv, const float* __restrict__ Wg) {
    size_t n = (size_t)(Dm / 2) * NPRE;
    for (size_t i = (size_t)blockIdx.x * blockDim.x + threadIdx.x; i < n;
         i += (size_t)gridDim.x * blockDim.x) {
        int col = (int)(i % NPRE);
        int k2 = (int)(i / NPRE);
        const float* src; int c;
        if (col < 1024)       { src = Wq; c = col;        }
        else if (col < 2048)  { src = Wk; c = col - 1024; }
        else if (col < 4096)  { src = Wv; c = col - 2048; }
        else                  { src = Wg; c = col - 4096; }
        int ncol = (col < 2048) ? 1024 : 2048;
        float v0 = src[(size_t)(2 * k2) * ncol + c];
        float v1 = src[(size_t)(2 * k2 + 1) * ncol + c];
        g_Wch[i] = __floats2half2_rn(v0, v1);
    }
}

// ---------------- pack Wo -> g_Woh [K/2][2048] half2 ----------------------------
__global__ void pack_wo_kernel(const float* __restrict__ Wo) {
    size_t n = (size_t)(Dm / 2) * Dm;
    for (size_t i = (size_t)blockIdx.x * blockDim.x + threadIdx.x; i < n;
         i += (size_t)gridDim.x * blockDim.x) {
        int col = (int)(i % Dm);
        int k2 = (int)(i / Dm);
        float v0 = Wo[(size_t)(2 * k2) * Dm + col];
        float v1 = Wo[(size_t)(2 * k2 + 1) * Dm + col];
        g_Woh[i] = __floats2half2_rn(v0, v1);
    }
}

// ---------------- pack x -> g_xh [M][K/2] half2 ---------------------------------
__global__ void pack_x_kernel(const float* __restrict__ x) {
    size_t n = (size_t)Bsz * Tn * Dm / 2;
    for (size_t i = (size_t)blockIdx.x * blockDim.x + threadIdx.x; i < n;
         i += (size_t)gridDim.x * blockDim.x) {
        float2 v = reinterpret_cast<const float2*>(x)[i];
        g_xh[i] = __floats2half2_rn(v.x, v.y);
    }
}

// ---------------- fused beta/g projection + activations ------------------------
__global__ void betag_fused_kernel(const float* __restrict__ x,
                                   const float* __restrict__ Wb, const float* __restrict__ Wa,
                                   const float* __restrict__ A_log,
                                   const float* __restrict__ dt_bias) {
    int wid = threadIdx.x >> 5, lane = threadIdx.x & 31;
    int row = blockIdx.x * 8 + wid;
    if (row >= Bsz * Tn) return;
    const float* xr = x + (size_t)row * Dm;
    float accB[8], accA[8];
#pragma unroll
    for (int h = 0; h < 8; h++) { accB[h] = 0.f; accA[h] = 0.f; }
    for (int k = lane; k < Dm; k += 32) {
        float xv = xr[k];
        const float4* wb = reinterpret_cast<const float4*>(Wb + (size_t)k * 8);
        const float4* wa = reinterpret_cast<const float4*>(Wa + (size_t)k * 8);
        float4 b0 = wb[0], b1 = wb[1], a0 = wa[0], a1 = wa[1];
        accB[0] += xv * b0.x; accB[1] += xv * b0.y; accB[2] += xv * b0.z; accB[3] += xv * b0.w;
        accB[4] += xv * b1.x; accB[5] += xv * b1.y; accB[6] += xv * b1.z; accB[7] += xv * b1.w;
        accA[0] += xv * a0.x; accA[1] += xv * a0.y; accA[2] += xv * a0.z; accA[3] += xv * a0.w;
        accA[4] += xv * a1.x; accA[5] += xv * a1.y; accA[6] += xv * a1.z; accA[7] += xv * a1.w;
    }
#pragma unroll
    for (int h = 0; h < 8; h++) {
#pragma unroll
        for (int m = 16; m; m >>= 1) {
            accB[h] += __shfl_xor_sync(0xffffffffu, accB[h], m);
            accA[h] += __shfl_xor_sync(0xffffffffu, accA[h], m);
        }
    }
    if (lane < 8) {
        int h = lane;
        float beta = 1.f / (1.f + expf(-accB[h]));
        float xg = accA[h] + dt_bias[h];
        float sp = (xg > 20.f) ? xg : log1pf(expf(xg));
        float gg = -expf(A_log[h]) * sp;
        int b = row / Tn, t = row % Tn;
        size_t o = (size_t)(b * Hh + h) * Tn + t;
        g_eg[o] = expf(gg);
        g_beta[o] = beta;
    }
}

// ---------------- causal dwconv + silu + l2norm for q/k ------------------------
__global__ void convnorm_qk_kernel(const float* __restrict__ convw,
                                   float* __restrict__ out, int off, float scale) {
    int idx = blockIdx.x;
    int h = idx % Hh;
    int t = (idx / Hh) % Tn;
    int b = idx / (Hh * Tn);
    int c = h * DK + threadIdx.x;

    const float* base = g_pre + (size_t)b * Tn * NPRE + off;
    float acc = 0.f;
#pragma unroll
    for (int i = 0; i < Wc; i++) {
        int tt = t - (Wc - 1) + i;
        if (tt >= 0) acc += base[(size_t)tt * NPRE + c] * convw[(size_t)c * Wc + i];
    }
    float s = siluf(acc);
    float ss = s * s;
#pragma unroll
    for (int m = 16; m; m >>= 1) ss += __shfl_xor_sync(0xffffffffu, ss, m);
    __shared__ float wsum[4];
    if ((threadIdx.x & 31) == 0) wsum[threadIdx.x >> 5] = ss;
    __syncthreads();
    float tot = wsum[0] + wsum[1] + wsum[2] + wsum[3];
    float r = rsqrtf(tot + 1e-6f) * scale;
    out[(((size_t)(b * Hh + h) * Tn) + t) * DK + threadIdx.x] = s * r;
}

// ---------------- causal dwconv + silu for v -----------------------------------
__global__ void convsilu_v_kernel(const float* __restrict__ convw) {
    size_t total = (size_t)Bsz * Tn * VC;
    for (size_t idx = (size_t)blockIdx.x * blockDim.x + threadIdx.x;
         idx < total; idx += (size_t)gridDim.x * blockDim.x) {
        int c = idx % VC;
        int t = (idx / VC) % Tn;
        int b = idx / ((size_t)VC * Tn);
        int h = c / DV, dv = c % DV;
        const float* base = g_pre + (size_t)b * Tn * NPRE + 2048;
        float acc = 0.f;
#pragma unroll
        for (int i = 0; i < Wc; i++) {
            int tt = t - (Wc - 1) + i;
            if (tt >= 0) acc += base[(size_t)tt * NPRE + c] * convw[(size_t)c * Wc + i];
        }
        g_vc[(((size_t)(b * Hh + h) * Tn) + t) * DV + dv] = siluf(acc);
    }
}

// ---------------- gated delta-rule recurrence ----------------------------------
// 256 threads: col = tid>>3 (0..31 value-columns of this DV tile), sub = tid&7
// (row group of 16). 2 warps per SMSP for latency hiding. Sub-run stride 20
// words (16B-aligned!) => aligned, conflict-free LDS.128 phases.
#define DVT 32
#define STAGE 32
#define SUBW2 20

__global__ void __launch_bounds__(256, 1) delta_kernel() {
    int bh = blockIdx.x;
    int vt = blockIdx.y;
    int tid = threadIdx.x;           // 256
    int col = tid >> 3;              // 0..31
    int sub = tid & 7;               // rows [sub*16, sub*16+16)
    int gcol = vt * DVT + col;

    const float* kb  = g_kn   + (size_t)bh * Tn * DK;
    const float* qb  = g_qn   + (size_t)bh * Tn * DK;
    const float* vb  = g_vc   + (size_t)bh * Tn * DV;
    const float* egb = g_eg   + (size_t)bh * Tn;
    const float* btb = g_beta + (size_t)bh * Tn;
    float* ob        = g_o    + (size_t)bh * Tn * DV;

    __shared__ float sK[STAGE][8 * SUBW2];   // 32 x 160
    __shared__ float sQ[STAGE][8 * SUBW2];
    __shared__ float sV[STAGE][DVT];
    __shared__ float sEg[STAGE];
    __shared__ float sBt[STAGE];

    float S[16];
#pragma unroll
    for (int i = 0; i < 16; i++) S[i] = 0.f;

    for (int c0 = 0; c0 < Tn; c0 += STAGE) {
        __syncthreads();
        // K/Q stage: 32 rows x 32 float4 each; sub-run r (= v4>>2) holds k-words
        // [r*16, r*16+16) at word offset r*20
#pragma unroll
        for (int l = 0; l < 4; l++) {
            int linear = tid + l * 256;
            int tl = linear >> 5;
            int v4 = linear & 31;
            float4 kv = reinterpret_cast<const float4*>(kb + (size_t)(c0 + tl) * DK)[v4];
            float4 qv = reinterpret_cast<const float4*>(qb + (size_t)(c0 + tl) * DK)[v4];
            int off = (v4 >> 2) * SUBW2 + (v4 & 3) * 4;
            *reinterpret_cast<float4*>(&sK[tl][off]) = kv;
            *reinterpret_cast<float4*>(&sQ[tl][off]) = qv;
        }
        // V stage: 32 rows x 8 float4 = 256 float4
        {
            int tl = tid >> 3;
            int v4 = tid & 7;
            float4 vv = reinterpret_cast<const float4*>(vb + (size_t)(c0 + tl) * DV + vt * DVT)[v4];
            *reinterpret_cast<float4*>(&sV[tl][v4 * 4]) = vv;
        }
        if (tid < STAGE) {
            sEg[tid] = egb[c0 + tid];
            sBt[tid] = btb[c0 + tid];
        }
        __syncthreads();

#pragma unroll 4
        for (int s = 0; s < STAGE; s++) {
            float eg = sEg[s];
            const float4* kr = reinterpret_cast<const float4*>(&sK[s][sub * SUBW2]);
            const float4* qr = reinterpret_cast<const float4*>(&sQ[s][sub * SUBW2]);

            float4 kq[4];
#pragma unroll
            for (int j = 0; j < 4; j++) kq[j] = kr[j];

            // p partial over this thread's 16 rows
            float p0 = 0.f, p1 = 0.f, p2 = 0.f, p3 = 0.f;
#pragma unroll
            for (int j = 0; j < 4; j++) {
                p0 += kq[j].x * S[4 * j + 0];
                p1 += kq[j].y * S[4 * j + 1];
                p2 += kq[j].z * S[4 * j + 2];
                p3 += kq[j].w * S[4 * j + 3];
            }
            float p = (p0 + p1) + (p2 + p3);
            p += __shfl_xor_sync(0xffffffffu, p, 1);
            p += __shfl_xor_sync(0xffffffffu, p, 2);
            p += __shfl_xor_sync(0xffffffffu, p, 4);

            float w = sBt[s] * (sV[s][col] - eg * p);

            // S = eg*S + k*w ; o partial = q . S_new
            float o0 = 0.f, o1 = 0.f, o2 = 0.f, o3 = 0.f;
#pragma unroll
            for (int j = 0; j < 4; j++) {
                float4 qv = qr[j];
                S[4 * j + 0] = eg * S[4 * j + 0] + kq[j].x * w;
                S[4 * j + 1] = eg * S[4 * j + 1] + kq[j].y * w;
                S[4 * j + 2] = eg * S[4 * j + 2] + kq[j].z * w;
                S[4 * j + 3] = eg * S[4 * j + 3] + kq[j].w * w;
                o0 += qv.x * S[4 * j + 0];
                o1 += qv.y * S[4 * j + 1];
                o2 += qv.z * S[4 * j + 2];
                o3 += qv.w * S[4 * j + 3];
            }
            float o = (o0 + o1) + (o2 + o3);
            o += __shfl_xor_sync(0xffffffffu, o, 1);
            o += __shfl_xor_sync(0xffffffffu, o, 2);
            o += __shfl_xor_sync(0xffffffffu, o, 4);
            if (sub == 0) ob[(size_t)(c0 + s) * DV + gcol] = o;
        }
    }
}

// ---------------- gated RMSNorm + silu(gate), half2 output ---------------------
__global__ void gatednorm_kernel(const float* __restrict__ g_norm_w) {
    int idx = blockIdx.x;
    int h = idx % Hh;
    int t = (idx / Hh) % Tn;
    int b = idx / (Hh * Tn);
    int dv = threadIdx.x * 2;
    size_t obase = ((size_t)(b * Hh + h) * Tn + t) * DV;
    float o0 = g_o[obase + dv];
    float o1 = g_o[obase + dv + 1];
    float ss = o0 * o0 + o1 * o1;
#pragma unroll
    for (int m = 16; m; m >>= 1) ss += __shfl_xor_sync(0xffffffffu, ss, m);
    __shared__ float wsum[4];
    if ((threadIdx.x & 31) == 0) wsum[threadIdx.x >> 5] = ss;
    __syncthreads();
    float tot = wsum[0] + wsum[1] + wsum[2] + wsum[3];
    float r = rsqrtf(tot * (1.f / DV) + 1e-5f);
    size_t gb = ((size_t)(b * Tn + t)) * NPRE + 4096 + h * DV + dv;
    float gt0 = g_pre[gb], gt1 = g_pre[gb + 1];
    float v0 = o0 * r * g_norm_w[dv] * siluf(gt0);
    float v1 = o1 * r * g_norm_w[dv + 1] * siluf(gt1);
    g_onh[((size_t)(b * Tn + t)) * (VC / 2) + (h * DV + dv) / 2] = __floats2half2_rn(v0, v1);
}

// ---------------- launch --------------------------------------------------------
extern "C" void kernel_launch(void* const* d_in, const int* in_sizes, int n_in,
                              void* d_out, int out_size) {
    const float* x       = (const float*)d_in[0];
    const float* Wq      = (const float*)d_in[1];
    const float* Wk      = (const float*)d_in[2];
    const float* Wv      = (const float*)d_in[3];
    const float* Wb      = (const float*)d_in[4];
    const float* Wa      = (const float*)d_in[5];
    const float* Wg      = (const float*)d_in[6];
    const float* Wo      = (const float*)d_in[7];
    const float* conv_q  = (const float*)d_in[8];
    const float* conv_k  = (const float*)d_in[9];
    const float* conv_v  = (const float*)d_in[10];
    const float* A_log   = (const float*)d_in[11];
    const float* dt_bias = (const float*)d_in[12];
    const float* gnw     = (const float*)d_in[13];
    float* out = (float*)d_out;

    float *pre, *qn, *kn;
    __half2 *Wch, *Woh, *xh, *onh;
    cudaGetSymbolAddress((void**)&pre, g_pre);
    cudaGetSymbolAddress((void**)&Wch, g_Wch);
    cudaGetSymbolAddress((void**)&Woh, g_Woh);
    cudaGetSymbolAddress((void**)&xh,  g_xh);
    cudaGetSymbolAddress((void**)&onh, g_onh);
    cudaGetSymbolAddress((void**)&qn,  g_qn);
    cudaGetSymbolAddress((void**)&kn,  g_kn);

    cudaFuncSetAttribute(gemm_h, cudaFuncAttributeMaxDynamicSharedMemorySize, SMEM_GEMMH);

    const int M = Bsz * Tn;   // 8192

    pack_w_kernel<<<1024, 256>>>(Wq, Wk, Wv, Wg);
    pack_wo_kernel<<<512, 256>>>(Wo);
    pack_x_kernel<<<1024, 256>>>(x);

    // big projection GEMM: pre[8192,6144] = xh @ Wch
    gemm_h<<<dim3(NPRE / TN, M / TM), 128, SMEM_GEMMH>>>(xh, Wch, pre, M, NPRE, Dm / 2);

    betag_fused_kernel<<<M / 8, 256>>>(x, Wb, Wa, A_log, dt_bias);

    convnorm_qk_kernel<<<Bsz * Tn * Hh, DK>>>(conv_q, qn, 0, 0.08838834764831845f);
    convnorm_qk_kernel<<<Bsz * Tn * Hh, DK>>>(conv_k, kn, 1024, 1.0f);
    convsilu_v_kernel<<<8192, 256>>>(conv_v);

    {
        dim3 grid(BH, DV / DVT);
        delta_kernel<<<grid, 256>>>();
    }

    gatednorm_kernel<<<Bsz * Tn * Hh, DV / 2>>>(gnw);

    // output GEMM: out[8192,2048] = onh @ Woh
    gemm_h<<<dim3(Dm / TN, M / TM), 128, SMEM_GEMMH>>>(onh, Woh, out, M, Dm, Dm / 2);
}

// round 9
// speedup vs baseline: 4.7909x; 1.0407x over previous
#include <cuda_runtime.h>
#include <cuda_fp16.h>
#include <math.h>
#include <stdint.h>

// Problem constants
#define Bsz 2
#define Tn 4096
#define Dm 2048
#define Hh 8
#define DK 128
#define DV 256
#define Wc 4
#define BH (Bsz*Hh)          // 16
#define QKC (Hh*DK)          // 1024
#define VC  (Hh*DV)          // 2048
#define NPRE 6144            // packed q|k|v|g columns

// ---------------- scratch (device globals; no allocations allowed) -------------
__device__ float   g_pre [(size_t)Bsz*Tn*NPRE];   // packed projections (fp32)
__device__ __half2 g_Wch [(size_t)(Dm/2)*NPRE];   // packed weights, half2 pairs along K
__device__ __half2 g_Woh [(size_t)(Dm/2)*Dm];     // Wo, half2 pairs along K
__device__ __half2 g_xh  [(size_t)Bsz*Tn*(Dm/2)]; // x, half2 pairs along K
__device__ __half2 g_onh [(size_t)Bsz*Tn*(VC/2)]; // gated-norm output, half2 pairs
__device__ float   g_qn  [(size_t)BH*Tn*DK];
__device__ float   g_kn  [(size_t)BH*Tn*DK];
__device__ float   g_vc  [(size_t)BH*Tn*DV];
__device__ float   g_eg  [(size_t)BH*Tn];
__device__ float   g_beta[(size_t)BH*Tn];
__device__ float   g_kk  [(size_t)BH*Tn];         // c_t = k_{t+1} . k_t
__device__ float   g_o   [(size_t)BH*Tn*DV];

__device__ __forceinline__ float siluf(float x) { return x / (1.f + __expf(-x)); }

__device__ __forceinline__ uint32_t smem_u32(const void* p) {
    uint32_t a;
    asm("{ .reg .u64 t; cvta.to.shared.u64 t, %1; cvt.u32.u64 %0, t; }" : "=r"(a) : "l"(p));
    return a;
}

#define CP_ASYNC16(dst, src) \
    asm volatile("cp.async.cg.shared.global [%0], [%1], 16;" \
        :: "r"((uint32_t)(dst)), "l"(src) : "memory")
#define CP_COMMIT() asm volatile("cp.async.commit_group;" ::: "memory")

// ============ fp16 m16n8k16 GEMM, fp32 accum, 4-stage cp.async pipeline ========
#define TM 128
#define TN 128
#define TKc2 16
#define AST2 20
#define BST2 136
#define STG_WORDS (TM*AST2 + TKc2*BST2)    // 4736
#define NST 4
#define SMEM_GEMMH (NST*STG_WORDS*4)       // 75776 bytes

__global__ void __launch_bounds__(128, 2) gemm_h(
    const __half2* __restrict__ A, const __half2* __restrict__ B,
    float* __restrict__ C, int Mtot, int Ntot, int K2tot) {
    extern __shared__ uint32_t sm[];
    const int tid = threadIdx.x, lane = tid & 31, wid = tid >> 5;
    const int wm = (wid & 1) * 64;
    const int wn = (wid >> 1) * 64;
    const int m0 = blockIdx.y * TM, n0 = blockIdx.x * TN;
    const int la3 = lane & 3, l4 = lane >> 2;

    float acc[4][8][4];
#pragma unroll
    for (int mt = 0; mt < 4; mt++)
#pragma unroll
        for (int nt = 0; nt < 8; nt++)
#pragma unroll
            for (int i = 0; i < 4; i++) acc[mt][nt][i] = 0.f;

    const int nch = K2tot / TKc2;

    auto load_stage = [&](int c, int s) {
        uint32_t* sa = sm + s * STG_WORDS;
        uint32_t* sb = sa + TM * AST2;
        const __half2* Ab = A + (size_t)m0 * K2tot + c * TKc2;
        const __half2* Bb = B + (size_t)(c * TKc2) * Ntot + n0;
#pragma unroll
        for (int i = 0; i < 4; i++) {
            int idx = tid + i * 128;
            int r = idx >> 2, cc = idx & 3;
            CP_ASYNC16(smem_u32(sa + r * AST2 + cc * 4), Ab + (size_t)r * K2tot + cc * 4);
        }
#pragma unroll
        for (int i = 0; i < 4; i++) {
            int idx = tid + i * 128;
            int r = idx >> 5, n4 = idx & 31;
            CP_ASYNC16(smem_u32(sb + r * BST2 + n4 * 4), Bb + (size_t)r * Ntot + n4 * 4);
        }
        CP_COMMIT();
    };

    load_stage(0, 0);
    load_stage(1, 1);
    load_stage(2, 2);

    for (int c = 0; c < nch; c++) {
        if (c + 3 <= nch)      asm volatile("cp.async.wait_group 2;" ::: "memory");
        else if (c + 2 == nch) asm volatile("cp.async.wait_group 1;" ::: "memory");
        else                   asm volatile("cp.async.wait_group 0;" ::: "memory");
        __syncthreads();
        if (c + 3 < nch) load_stage(c + 3, (c + 3) % NST);

        const uint32_t* sa = sm + (c % NST) * STG_WORDS;
        const uint32_t* sb = sa + TM * AST2;
#pragma unroll
        for (int ks = 0; ks < 2; ks++) {
            uint32_t a[4][4];
#pragma unroll
            for (int mt = 0; mt < 4; mt++) {
                int mm = wm + mt * 16 + l4;
                int base = mm * AST2 + ks * 8 + la3;
                a[mt][0] = sa[base];
                a[mt][1] = sa[base + 8 * AST2];
                a[mt][2] = sa[base + 4];
                a[mt][3] = sa[base + 8 * AST2 + 4];
            }
            uint32_t b[8][2];
#pragma unroll
            for (int nt = 0; nt < 8; nt++) {
                int nn = wn + nt * 8 + l4;
                b[nt][0] = sb[(ks * 8 + la3) * BST2 + nn];
                b[nt][1] = sb[(ks * 8 + la3 + 4) * BST2 + nn];
            }
#pragma unroll
            for (int mt = 0; mt < 4; mt++)
#pragma unroll
                for (int nt = 0; nt < 8; nt++) {
                    asm volatile(
                        "mma.sync.aligned.m16n8k16.row.col.f32.f16.f16.f32 "
                        "{%0,%1,%2,%3}, {%4,%5,%6,%7}, {%8,%9}, {%0,%1,%2,%3};"
                        : "+f"(acc[mt][nt][0]), "+f"(acc[mt][nt][1]),
                          "+f"(acc[mt][nt][2]), "+f"(acc[mt][nt][3])
                        : "r"(a[mt][0]), "r"(a[mt][1]), "r"(a[mt][2]), "r"(a[mt][3]),
                          "r"(b[nt][0]), "r"(b[nt][1]));
                }
        }
    }

#pragma unroll
    for (int mt = 0; mt < 4; mt++) {
#pragma unroll
        for (int nt = 0; nt < 8; nt++) {
            int row = m0 + wm + mt * 16 + l4;
            int col = n0 + wn + nt * 8 + la3 * 2;
            *reinterpret_cast<float2*>(&C[(size_t)row * Ntot + col]) =
                make_float2(acc[mt][nt][0], acc[mt][nt][1]);
            *reinterpret_cast<float2*>(&C[(size_t)(row + 8) * Ntot + col]) =
                make_float2(acc[mt][nt][2], acc[mt][nt][3]);
        }
    }
}

// ---------------- pack Wq|Wk|Wv|Wg -> g_Wch [K/2][6144] half2 -------------------
__global__ void pack_w_kernel(const float* __restrict__ Wq, const float* __restrict__ Wk,
                              const float* __restrict__ Wv, const float* __restrict__ Wg) {
    size_t n = (size_t)(Dm / 2) * NPRE;
    for (size_t i = (size_t)blockIdx.x * blockDim.x + threadIdx.x; i < n;
         i += (size_t)gridDim.x * blockDim.x) {
        int col = (int)(i % NPRE);
        int k2 = (int)(i / NPRE);
        const float* src; int c;
        if (col < 1024)       { src = Wq; c = col;        }
        else if (col < 2048)  { src = Wk; c = col - 1024; }
        else if (col < 4096)  { src = Wv; c = col - 2048; }
        else                  { src = Wg; c = col - 4096; }
        int ncol = (col < 2048) ? 1024 : 2048;
        float v0 = src[(size_t)(2 * k2) * ncol + c];
        float v1 = src[(size_t)(2 * k2 + 1) * ncol + c];
        g_Wch[i] = __floats2half2_rn(v0, v1);
    }
}

__global__ void pack_wo_kernel(const float* __restrict__ Wo) {
    size_t n = (size_t)(Dm / 2) * Dm;
    for (size_t i = (size_t)blockIdx.x * blockDim.x + threadIdx.x; i < n;
         i += (size_t)gridDim.x * blockDim.x) {
        int col = (int)(i % Dm);
        int k2 = (int)(i / Dm);
        float v0 = Wo[(size_t)(2 * k2) * Dm + col];
        float v1 = Wo[(size_t)(2 * k2 + 1) * Dm + col];
        g_Woh[i] = __floats2half2_rn(v0, v1);
    }
}

__global__ void pack_x_kernel(const float* __restrict__ x) {
    size_t n = (size_t)Bsz * Tn * Dm / 2;
    for (size_t i = (size_t)blockIdx.x * blockDim.x + threadIdx.x; i < n;
         i += (size_t)gridDim.x * blockDim.x) {
        float2 v = reinterpret_cast<const float2*>(x)[i];
        g_xh[i] = __floats2half2_rn(v.x, v.y);
    }
}

// ---------------- fused beta/g projection + activations ------------------------
__global__ void betag_fused_kernel(const float* __restrict__ x,
                                   const float* __restrict__ Wb, const float* __restrict__ Wa,
                                   const float* __restrict__ A_log,
                                   const float* __restrict__ dt_bias) {
    int wid = threadIdx.x >> 5, lane = threadIdx.x & 31;
    int row = blockIdx.x * 8 + wid;
    if (row >= Bsz * Tn) return;
    const float* xr = x + (size_t)row * Dm;
    float accB[8], accA[8];
#pragma unroll
    for (int h = 0; h < 8; h++) { accB[h] = 0.f; accA[h] = 0.f; }
    for (int k = lane; k < Dm; k += 32) {
        float xv = xr[k];
        const float4* wb = reinterpret_cast<const float4*>(Wb + (size_t)k * 8);
        const float4* wa = reinterpret_cast<const float4*>(Wa + (size_t)k * 8);
        float4 b0 = wb[0], b1 = wb[1], a0 = wa[0], a1 = wa[1];
        accB[0] += xv * b0.x; accB[1] += xv * b0.y; accB[2] += xv * b0.z; accB[3] += xv * b0.w;
        accB[4] += xv * b1.x; accB[5] += xv * b1.y; accB[6] += xv * b1.z; accB[7] += xv * b1.w;
        accA[0] += xv * a0.x; accA[1] += xv * a0.y; accA[2] += xv * a0.z; accA[3] += xv * a0.w;
        accA[4] += xv * a1.x; accA[5] += xv * a1.y; accA[6] += xv * a1.z; accA[7] += xv * a1.w;
    }
#pragma unroll
    for (int h = 0; h < 8; h++) {
#pragma unroll
        for (int m = 16; m; m >>= 1) {
            accB[h] += __shfl_xor_sync(0xffffffffu, accB[h], m);
            accA[h] += __shfl_xor_sync(0xffffffffu, accA[h], m);
        }
    }
    if (lane < 8) {
        int h = lane;
        float beta = 1.f / (1.f + expf(-accB[h]));
        float xg = accA[h] + dt_bias[h];
        float sp = (xg > 20.f) ? xg : log1pf(expf(xg));
        float gg = -expf(A_log[h]) * sp;
        int b = row / Tn, t = row % Tn;
        size_t o = (size_t)(b * Hh + h) * Tn + t;
        g_eg[o] = expf(gg);
        g_beta[o] = beta;
    }
}

// ---------------- causal dwconv + silu + l2norm for q/k ------------------------
__global__ void convnorm_qk_kernel(const float* __restrict__ convw,
                                   float* __restrict__ out, int off, float scale) {
    int idx = blockIdx.x;
    int h = idx % Hh;
    int t = (idx / Hh) % Tn;
    int b = idx / (Hh * Tn);
    int c = h * DK + threadIdx.x;

    const float* base = g_pre + (size_t)b * Tn * NPRE + off;
    float acc = 0.f;
#pragma unroll
    for (int i = 0; i < Wc; i++) {
        int tt = t - (Wc - 1) + i;
        if (tt >= 0) acc += base[(size_t)tt * NPRE + c] * convw[(size_t)c * Wc + i];
    }
    float s = siluf(acc);
    float ss = s * s;
#pragma unroll
    for (int m = 16; m; m >>= 1) ss += __shfl_xor_sync(0xffffffffu, ss, m);
    __shared__ float wsum[4];
    if ((threadIdx.x & 31) == 0) wsum[threadIdx.x >> 5] = ss;
    __syncthreads();
    float tot = wsum[0] + wsum[1] + wsum[2] + wsum[3];
    float r = rsqrtf(tot + 1e-6f) * scale;
    out[(((size_t)(b * Hh + h) * Tn) + t) * DK + threadIdx.x] = s * r;
}

// ---------------- causal dwconv + silu for v -----------------------------------
__global__ void convsilu_v_kernel(const float* __restrict__ convw) {
    size_t total = (size_t)Bsz * Tn * VC;
    for (size_t idx = (size_t)blockIdx.x * blockDim.x + threadIdx.x;
         idx < total; idx += (size_t)gridDim.x * blockDim.x) {
        int c = idx % VC;
        int t = (idx / VC) % Tn;
        int b = idx / ((size_t)VC * Tn);
        int h = c / DV, dv = c % DV;
        const float* base = g_pre + (size_t)b * Tn * NPRE + 2048;
        float acc = 0.f;
#pragma unroll
        for (int i = 0; i < Wc; i++) {
            int tt = t - (Wc - 1) + i;
            if (tt >= 0) acc += base[(size_t)tt * NPRE + c] * convw[(size_t)c * Wc + i];
        }
        g_vc[(((size_t)(b * Hh + h) * Tn) + t) * DV + dv] = siluf(acc);
    }
}

// ---------------- k_{t+1} . k_t dots --------------------------------------------
__global__ void kk_kernel() {
    int wid = threadIdx.x >> 5, lane = threadIdx.x & 31;
    int idx = blockIdx.x * 8 + wid;              // bh*Tn + t
    if (idx >= BH * Tn) return;
    int t = idx & (Tn - 1);
    float s = 0.f;
    if (t + 1 < Tn) {
        const float* k0 = g_kn + (size_t)idx * DK;
        float4 a = reinterpret_cast<const float4*>(k0)[lane];
        float4 b = reinterpret_cast<const float4*>(k0 + DK)[lane];
        s = a.x * b.x + a.y * b.y + a.z * b.z + a.w * b.w;
    }
#pragma unroll
    for (int m = 16; m; m >>= 1) s += __shfl_xor_sync(0xffffffffu, s, m);
    if (lane == 0) g_kk[idx] = s;
}

// ---------------- gated delta-rule recurrence (pipelined) -----------------------
// 256 threads: col = tid>>3 (32 value-cols), sub = tid&7 (16 rows each).
// Critical path broken via p_{t+1} = eg_t*(k_{t+1}.S_{t-1}) + (k_{t+1}.k_t)*w_t;
// o reductions deferred to a per-stage batched pass through smem.
#define DVT 32
#define STAGE 32
#define SUBW2 20
#define SKROW 160                  // 8*SUBW2
#define OFF_SK 0
#define OFF_SQ (OFF_SK + (STAGE+1)*SKROW)   // 5280
#define OFF_SV (OFF_SQ + STAGE*SKROW)       // 10400
#define OFF_OP (OFF_SV + STAGE*DVT)         // 11424
#define OFF_EG (OFF_OP + STAGE*256)         // 19616
#define OFF_BT (OFF_EG + STAGE)
#define OFF_CC (OFF_BT + STAGE)
#define DELTA_SMEM ((OFF_CC + STAGE) * 4)   // 78848 bytes

__global__ void __launch_bounds__(256, 1) delta_kernel() {
    extern __shared__ float dsm[];
    float* sK  = dsm + OFF_SK;
    float* sQ  = dsm + OFF_SQ;
    float* sV  = dsm + OFF_SV;
    float* oP  = dsm + OFF_OP;
    float* sEg = dsm + OFF_EG;
    float* sBt = dsm + OFF_BT;
    float* sC  = dsm + OFF_CC;

    int bh = blockIdx.x;
    int vt = blockIdx.y;
    int tid = threadIdx.x;           // 256
    int col = tid >> 3;              // 0..31
    int sub = tid & 7;               // rows [sub*16, sub*16+16)

    const float* kb  = g_kn   + (size_t)bh * Tn * DK;
    const float* qb  = g_qn   + (size_t)bh * Tn * DK;
    const float* vb  = g_vc   + (size_t)bh * Tn * DV;
    const float* egb = g_eg   + (size_t)bh * Tn;
    const float* btb = g_beta + (size_t)bh * Tn;
    const float* ccb = g_kk   + (size_t)bh * Tn;
    float* ob        = g_o    + (size_t)bh * Tn * DV;

    float S[16];
#pragma unroll
    for (int i = 0; i < 16; i++) S[i] = 0.f;
    float E_prev = 0.f, w_prev = 0.f, c_prev = 0.f, eg_prev = 0.f;

    for (int c0 = 0; c0 < Tn; c0 += STAGE) {
        __syncthreads();
        // K rows 0..32 (33), Q rows 0..31
#pragma unroll
        for (int l = 0; l < 4; l++) {
            int linear = tid + l * 256;
            int tl = linear >> 5;
            int v4 = linear & 31;
            float4 kv = reinterpret_cast<const float4*>(kb + (size_t)(c0 + tl) * DK)[v4];
            float4 qv = reinterpret_cast<const float4*>(qb + (size_t)(c0 + tl) * DK)[v4];
            int off = (v4 >> 2) * SUBW2 + (v4 & 3) * 4;
            *reinterpret_cast<float4*>(&sK[tl * SKROW + off]) = kv;
            *reinterpret_cast<float4*>(&sQ[tl * SKROW + off]) = qv;
        }
        if (tid < 32) {
            int row = c0 + 32; if (row > Tn - 1) row = Tn - 1;
            float4 kv = reinterpret_cast<const float4*>(kb + (size_t)row * DK)[tid];
            int off = (tid >> 2) * SUBW2 + (tid & 3) * 4;
            *reinterpret_cast<float4*>(&sK[32 * SKROW + off]) = kv;
        }
        {
            int tl = tid >> 3;
            int v4 = tid & 7;
            float4 vv = reinterpret_cast<const float4*>(vb + (size_t)(c0 + tl) * DV + vt * DVT)[v4];
            *reinterpret_cast<float4*>(&sV[tl * DVT + v4 * 4]) = vv;
        }
        if (tid < STAGE) {
            sEg[tid] = egb[c0 + tid];
            sBt[tid] = btb[c0 + tid];
            sC[tid]  = ccb[c0 + tid];
        }
        __syncthreads();

        float4 kq[4];
        {
            const float4* kr = reinterpret_cast<const float4*>(&sK[sub * SUBW2]);
#pragma unroll
            for (int j = 0; j < 4; j++) kq[j] = kr[j];
        }

#pragma unroll 4
        for (int s = 0; s < STAGE; s++) {
            float eg = sEg[s], bt = sBt[s], cc = sC[s];
            float v = sV[s * DVT + col];

            // scalar recurrence: p_t = eg_{t-1}*E_{t-1} + c_{t-1}*w_{t-1}
            float p = eg_prev * E_prev + c_prev * w_prev;
            float w = bt * (v - eg * p);

            // k_{t+1}
            float4 kn[4];
            const float4* krn = reinterpret_cast<const float4*>(&sK[(s + 1) * SKROW + sub * SUBW2]);
#pragma unroll
            for (int j = 0; j < 4; j++) kn[j] = krn[j];

            // E_t = k_{t+1} . S_{t-1} (pre-update), overlaps with w chain
            float e0 = 0.f, e1 = 0.f, e2 = 0.f, e3 = 0.f;
#pragma unroll
            for (int j = 0; j < 4; j++) {
                e0 += kn[j].x * S[4 * j + 0];
                e1 += kn[j].y * S[4 * j + 1];
                e2 += kn[j].z * S[4 * j + 2];
                e3 += kn[j].w * S[4 * j + 3];
            }
            float E = (e0 + e1) + (e2 + e3);
            E += __shfl_xor_sync(0xffffffffu, E, 1);
            E += __shfl_xor_sync(0xffffffffu, E, 2);
            E += __shfl_xor_sync(0xffffffffu, E, 4);

            // update S with k_t; o partial with q_t (deferred reduction)
            const float4* qr = reinterpret_cast<const float4*>(&sQ[s * SKROW + sub * SUBW2]);
            float o0 = 0.f, o1 = 0.f, o2 = 0.f, o3 = 0.f;
#pragma unroll
            for (int j = 0; j < 4; j++) {
                float4 qv = qr[j];
                S[4 * j + 0] = eg * S[4 * j + 0] + kq[j].x * w;
                S[4 * j + 1] = eg * S[4 * j + 1] + kq[j].y * w;
                S[4 * j + 2] = eg * S[4 * j + 2] + kq[j].z * w;
                S[4 * j + 3] = eg * S[4 * j + 3] + kq[j].w * w;
                o0 += qv.x * S[4 * j + 0];
                o1 += qv.y * S[4 * j + 1];
                o2 += qv.z * S[4 * j + 2];
                o3 += qv.w * S[4 * j + 3];
            }
            oP[s * 256 + col * 8 + sub] = (o0 + o1) + (o2 + o3);

            E_prev = E; w_prev = w; c_prev = cc; eg_prev = eg;
#pragma unroll
            for (int j = 0; j < 4; j++) kq[j] = kn[j];
        }
        __syncthreads();

        // batched o reduction + store: 1024 outputs, 4 per thread
#pragma unroll
        for (int r = 0; r < 4; r++) {
            int idx = r * 256 + tid;
            int t = idx >> 5, cl = idx & 31;
            const float* b = &oP[t * 256 + cl * 8];
            float sum = ((b[0] + b[1]) + (b[2] + b[3])) + ((b[4] + b[5]) + (b[6] + b[7]));
            ob[(size_t)(c0 + t) * DV + vt * DVT + cl] = sum;
        }
    }
}

// ---------------- gated RMSNorm + silu(gate), half2 output ---------------------
__global__ void gatednorm_kernel(const float* __restrict__ g_norm_w) {
    int idx = blockIdx.x;
    int h = idx % Hh;
    int t = (idx / Hh) % Tn;
    int b = idx / (Hh * Tn);
    int dv = threadIdx.x * 2;
    size_t obase = ((size_t)(b * Hh + h) * Tn + t) * DV;
    float o0 = g_o[obase + dv];
    float o1 = g_o[obase + dv + 1];
    float ss = o0 * o0 + o1 * o1;
#pragma unroll
    for (int m = 16; m; m >>= 1) ss += __shfl_xor_sync(0xffffffffu, ss, m);
    __shared__ float wsum[4];
    if ((threadIdx.x & 31) == 0) wsum[threadIdx.x >> 5] = ss;
    __syncthreads();
    float tot = wsum[0] + wsum[1] + wsum[2] + wsum[3];
    float r = rsqrtf(tot * (1.f / DV) + 1e-5f);
    size_t gb = ((size_t)(b * Tn + t)) * NPRE + 4096 + h * DV + dv;
    float gt0 = g_pre[gb], gt1 = g_pre[gb + 1];
    float v0 = o0 * r * g_norm_w[dv] * siluf(gt0);
    float v1 = o1 * r * g_norm_w[dv + 1] * siluf(gt1);
    g_onh[((size_t)(b * Tn + t)) * (VC / 2) + (h * DV + dv) / 2] = __floats2half2_rn(v0, v1);
}

// ---------------- launch --------------------------------------------------------
extern "C" void kernel_launch(void* const* d_in, const int* in_sizes, int n_in,
                              void* d_out, int out_size) {
    const float* x       = (const float*)d_in[0];
    const float* Wq      = (const float*)d_in[1];
    const float* Wk      = (const float*)d_in[2];
    const float* Wv      = (const float*)d_in[3];
    const float* Wb      = (const float*)d_in[4];
    const float* Wa      = (const float*)d_in[5];
    const float* Wg      = (const float*)d_in[6];
    const float* Wo      = (const float*)d_in[7];
    const float* conv_q  = (const float*)d_in[8];
    const float* conv_k  = (const float*)d_in[9];
    const float* conv_v  = (const float*)d_in[10];
    const float* A_log   = (const float*)d_in[11];
    const float* dt_bias = (const float*)d_in[12];
    const float* gnw     = (const float*)d_in[13];
    float* out = (float*)d_out;

    float *pre, *qn, *kn;
    __half2 *Wch, *Woh, *xh, *onh;
    cudaGetSymbolAddress((void**)&pre, g_pre);
    cudaGetSymbolAddress((void**)&Wch, g_Wch);
    cudaGetSymbolAddress((void**)&Woh, g_Woh);
    cudaGetSymbolAddress((void**)&xh,  g_xh);
    cudaGetSymbolAddress((void**)&onh, g_onh);
    cudaGetSymbolAddress((void**)&qn,  g_qn);
    cudaGetSymbolAddress((void**)&kn,  g_kn);

    cudaFuncSetAttribute(gemm_h, cudaFuncAttributeMaxDynamicSharedMemorySize, SMEM_GEMMH);
    cudaFuncSetAttribute(delta_kernel, cudaFuncAttributeMaxDynamicSharedMemorySize, DELTA_SMEM);

    const int M = Bsz * Tn;   // 8192

    pack_w_kernel<<<1024, 256>>>(Wq, Wk, Wv, Wg);
    pack_wo_kernel<<<512, 256>>>(Wo);
    pack_x_kernel<<<1024, 256>>>(x);

    // big projection GEMM: pre[8192,6144] = xh @ Wch
    gemm_h<<<dim3(NPRE / TN, M / TM), 128, SMEM_GEMMH>>>(xh, Wch, pre, M, NPRE, Dm / 2);

    betag_fused_kernel<<<M / 8, 256>>>(x, Wb, Wa, A_log, dt_bias);

    convnorm_qk_kernel<<<Bsz * Tn * Hh, DK>>>(conv_q, qn, 0, 0.08838834764831845f);
    convnorm_qk_kernel<<<Bsz * Tn * Hh, DK>>>(conv_k, kn, 1024, 1.0f);
    convsilu_v_kernel<<<8192, 256>>>(conv_v);

    kk_kernel<<<BH * Tn / 8, 256>>>();

    {
        dim3 grid(BH, DV / DVT);
        delta_kernel<<<grid, 256, DELTA_SMEM>>>();
    }

    gatednorm_kernel<<<Bsz * Tn * Hh, DV / 2>>>(gnw);

    // output GEMM: out[8192,2048] = onh @ Woh
    gemm_h<<<dim3(Dm / TN, M / TM), 128, SMEM_GEMMH>>>(onh, Woh, out, M, Dm, Dm / 2);
}